// round 4
// baseline (speedup 1.0000x reference)
#include <cuda_runtime.h>
#include <cstddef>

// Problem constants
#define B_   64
#define S_   256
#define H_   512
#define E_   256
#define V_   32000
#define ML_  32256
#define D2H  1024          // 2*H
#define XW   1536          // 3*H (width of x, gi, gh)
#define X1W  1280          // 2*H + E

// packed fp32x2 FMA (Blackwell): c = a*b + c, elementwise on 2-lane fp32 pairs.
// "+l" ties accumulator in-place -> no MOVs around the FFMA2.
#define FMA2(c, a, b) asm("fma.rn.f32x2 %0, %1, %2, %0;" \
    : "+l"(c) : "l"(a), "l"(b))

// ---------------- scratch (device globals; no allocation allowed) ----------------
__device__ float g_attn_strength[B_ * D2H];
__device__ float g_scores[B_ * S_];          // attn scores -> weights (in place)
__device__ float g_x1[B_ * X1W];             // [context | embedding]
__device__ float g_x [B_ * XW];              // [attn_reading | select_reading]
__device__ float g_gi[B_ * XW];
__device__ float g_gh[B_ * XW];
__device__ float g_state[B_ * H_];
__device__ float g_logits[B_ * ML_];         // [score_g | score_c] -> probs (in place)
__device__ float g_part[2 * B_ * V_];        // split-K partials (largest: score_g k=2)
__device__ float g_scpart[4 * B_ * S_];      // score_c N-tile partials

// ---------------- generic fp32 GEMM: C[64,N] = A[64,K] @ B[N,K]^T (+bias) --------
// BM=64, BN=128, BK=16, 256 threads, 4x8 microtile, FFMA2 inner loop,
// double-buffered smem: ONE __syncthreads per K-tile, gmem prefetch in regs.
__global__ void __launch_bounds__(256) gemm64_kernel(
    const float* __restrict__ A, int lda,
    const float* __restrict__ Bm,
    const float* __restrict__ bias,
    float* __restrict__ C, int ldc,
    int N, int K, int kSplit)
{
    __shared__ __align__(16) float2 As2[2][16][64];   // A values duplicated (v,v)
    __shared__ __align__(16) float  Bs[2][16][128];
    const int tid  = threadIdx.x;
    const int tx   = tid & 15;
    const int ty   = tid >> 4;
    const int arow = tid >> 2;           // 0..63
    const int akv  = (tid & 3) * 4;      // 0,4,8,12
    const int n0   = blockIdx.x * 128;
    const int kLen = K / kSplit;
    const int k0   = blockIdx.y * kLen;

    const float* Ag  = A  + (size_t)arow * lda + k0 + akv;
    const float* Bg0 = Bm + (size_t)(n0 + arow) * K + k0 + akv;
    const float* Bg1 = Bm + (size_t)(n0 + 64 + arow) * K + k0 + akv;

    unsigned long long acc[4][4];        // 4 rows x 4 col-pairs, packed fp32x2
    #pragma unroll
    for (int i = 0; i < 4; i++)
        #pragma unroll
        for (int p = 0; p < 4; p++) acc[i][p] = 0ull;

    const int nTiles = kLen >> 4;

    // prologue: tile 0 -> buf 0
    {
        float4 av  = *(const float4*)(Ag);
        float4 bv0 = *(const float4*)(Bg0);
        float4 bv1 = *(const float4*)(Bg1);
        As2[0][akv+0][arow] = make_float2(av.x, av.x);
        As2[0][akv+1][arow] = make_float2(av.y, av.y);
        As2[0][akv+2][arow] = make_float2(av.z, av.z);
        As2[0][akv+3][arow] = make_float2(av.w, av.w);
        Bs[0][akv+0][arow] = bv0.x; Bs[0][akv+1][arow] = bv0.y;
        Bs[0][akv+2][arow] = bv0.z; Bs[0][akv+3][arow] = bv0.w;
        Bs[0][akv+0][64+arow] = bv1.x; Bs[0][akv+1][64+arow] = bv1.y;
        Bs[0][akv+2][64+arow] = bv1.z; Bs[0][akv+3][64+arow] = bv1.w;
    }
    __syncthreads();

    for (int t = 0; t < nTiles; t++) {
        const int cur = t & 1;
        float4 av, bv0, bv1;
        const bool more = (t + 1 < nTiles);
        if (more) {                       // prefetch next tile (overlaps compute)
            int kb = (t + 1) << 4;
            av  = *(const float4*)(Ag  + kb);
            bv0 = *(const float4*)(Bg0 + kb);
            bv1 = *(const float4*)(Bg1 + kb);
        }
        #pragma unroll
        for (int k = 0; k < 16; k++) {
            ulonglong2 a01 = *(const ulonglong2*)&As2[cur][k][ty*4];
            ulonglong2 a23 = *(const ulonglong2*)&As2[cur][k][ty*4+2];
            ulonglong2 b01 = *(const ulonglong2*)&Bs[cur][k][tx*8];
            ulonglong2 b23 = *(const ulonglong2*)&Bs[cur][k][tx*8+4];
            unsigned long long ar[4] = {a01.x, a01.y, a23.x, a23.y};
            unsigned long long br[4] = {b01.x, b01.y, b23.x, b23.y};
            #pragma unroll
            for (int i = 0; i < 4; i++)
                #pragma unroll
                for (int p = 0; p < 4; p++)
                    FMA2(acc[i][p], ar[i], br[p]);
        }
        if (more) {
            const int nxt = cur ^ 1;
            As2[nxt][akv+0][arow] = make_float2(av.x, av.x);
            As2[nxt][akv+1][arow] = make_float2(av.y, av.y);
            As2[nxt][akv+2][arow] = make_float2(av.z, av.z);
            As2[nxt][akv+3][arow] = make_float2(av.w, av.w);
            Bs[nxt][akv+0][arow] = bv0.x; Bs[nxt][akv+1][arow] = bv0.y;
            Bs[nxt][akv+2][arow] = bv0.z; Bs[nxt][akv+3][arow] = bv0.w;
            Bs[nxt][akv+0][64+arow] = bv1.x; Bs[nxt][akv+1][64+arow] = bv1.y;
            Bs[nxt][akv+2][64+arow] = bv1.z; Bs[nxt][akv+3][64+arow] = bv1.w;
        }
        __syncthreads();
    }

    if (kSplit == 1) {
        #pragma unroll
        for (int i = 0; i < 4; i++) {
            int r = ty*4 + i;
            #pragma unroll
            for (int p = 0; p < 4; p++) {
                int c = n0 + tx*8 + p*2;
                float lo = __uint_as_float((unsigned)acc[i][p]);
                float hi = __uint_as_float((unsigned)(acc[i][p] >> 32));
                if (bias) { lo += bias[c]; hi += bias[c+1]; }
                C[(size_t)r * ldc + c]     = lo;
                C[(size_t)r * ldc + c + 1] = hi;
            }
        }
    } else {
        float* P = g_part + (size_t)blockIdx.y * 64 * N;
        #pragma unroll
        for (int i = 0; i < 4; i++) {
            int r = ty*4 + i;
            #pragma unroll
            for (int p = 0; p < 4; p++) {
                int c = n0 + tx*8 + p*2;
                P[(size_t)r * N + c]     = __uint_as_float((unsigned)acc[i][p]);
                P[(size_t)r * N + c + 1] = __uint_as_float((unsigned)(acc[i][p] >> 32));
            }
        }
    }
}

// Fixed-order (deterministic) split-K reduction: C = bias + sum_z part[z]
__global__ void splitk_reduce(const float* __restrict__ bias,
                              float* __restrict__ C, int ldc, int N, int kSplit)
{
    int idx = blockIdx.x * blockDim.x + threadIdx.x;
    int total = 64 * N;
    if (idx >= total) return;
    int m = idx / N, n = idx - m * N;
    float s = bias ? bias[n] : 0.f;
    for (int z = 0; z < kSplit; z++) s += g_part[(size_t)z * total + idx];
    C[(size_t)m * ldc + n] = s;
}

// ---------------- score_c fused kernel -------------------------------------------
// For batch b, s-tile (64 rows), h-tile (128 cols):
//   F = enc_tile @ W_c^T ; partial[s] = sum_h tanh(F + b_c[h]) * state[b,h]
// Double-buffered like gemm64_kernel.
__global__ void __launch_bounds__(256) score_c_kernel(
    const float* __restrict__ enc,
    const float* __restrict__ W_c,
    const float* __restrict__ b_c,
    const float* __restrict__ state)
{
    __shared__ __align__(16) float2 As2[2][16][64];
    __shared__ __align__(16) float  Bs[2][16][128];
    __shared__ float red[64][17];
    const int tid  = threadIdx.x;
    const int tx   = tid & 15;
    const int ty   = tid >> 4;
    const int arow = tid >> 2;
    const int akv  = (tid & 3) * 4;
    const int s0   = blockIdx.x * 64;       // 0..3
    const int n0   = blockIdx.y * 128;      // 0..3
    const int b    = blockIdx.z;
    const int K    = D2H;                   // 1024

    const float* A   = enc + ((size_t)b * S_ + s0) * K;
    const float* Ag  = A   + (size_t)arow * K + akv;
    const float* Bg0 = W_c + (size_t)(n0 + arow) * K + akv;
    const float* Bg1 = W_c + (size_t)(n0 + 64 + arow) * K + akv;

    unsigned long long acc[4][4];
    #pragma unroll
    for (int i = 0; i < 4; i++)
        #pragma unroll
        for (int p = 0; p < 4; p++) acc[i][p] = 0ull;

    const int nTiles = K >> 4;   // 64

    {
        float4 av  = *(const float4*)(Ag);
        float4 bv0 = *(const float4*)(Bg0);
        float4 bv1 = *(const float4*)(Bg1);
        As2[0][akv+0][arow] = make_float2(av.x, av.x);
        As2[0][akv+1][arow] = make_float2(av.y, av.y);
        As2[0][akv+2][arow] = make_float2(av.z, av.z);
        As2[0][akv+3][arow] = make_float2(av.w, av.w);
        Bs[0][akv+0][arow] = bv0.x; Bs[0][akv+1][arow] = bv0.y;
        Bs[0][akv+2][arow] = bv0.z; Bs[0][akv+3][arow] = bv0.w;
        Bs[0][akv+0][64+arow] = bv1.x; Bs[0][akv+1][64+arow] = bv1.y;
        Bs[0][akv+2][64+arow] = bv1.z; Bs[0][akv+3][64+arow] = bv1.w;
    }
    __syncthreads();

    for (int t = 0; t < nTiles; t++) {
        const int cur = t & 1;
        float4 av, bv0, bv1;
        const bool more = (t + 1 < nTiles);
        if (more) {
            int kb = (t + 1) << 4;
            av  = *(const float4*)(Ag  + kb);
            bv0 = *(const float4*)(Bg0 + kb);
            bv1 = *(const float4*)(Bg1 + kb);
        }
        #pragma unroll
        for (int k = 0; k < 16; k++) {
            ulonglong2 a01 = *(const ulonglong2*)&As2[cur][k][ty*4];
            ulonglong2 a23 = *(const ulonglong2*)&As2[cur][k][ty*4+2];
            ulonglong2 b01 = *(const ulonglong2*)&Bs[cur][k][tx*8];
            ulonglong2 b23 = *(const ulonglong2*)&Bs[cur][k][tx*8+4];
            unsigned long long ar[4] = {a01.x, a01.y, a23.x, a23.y};
            unsigned long long br[4] = {b01.x, b01.y, b23.x, b23.y};
            #pragma unroll
            for (int i = 0; i < 4; i++)
                #pragma unroll
                for (int p = 0; p < 4; p++)
                    FMA2(acc[i][p], ar[i], br[p]);
        }
        if (more) {
            const int nxt = cur ^ 1;
            As2[nxt][akv+0][arow] = make_float2(av.x, av.x);
            As2[nxt][akv+1][arow] = make_float2(av.y, av.y);
            As2[nxt][akv+2][arow] = make_float2(av.z, av.z);
            As2[nxt][akv+3][arow] = make_float2(av.w, av.w);
            Bs[nxt][akv+0][arow] = bv0.x; Bs[nxt][akv+1][arow] = bv0.y;
            Bs[nxt][akv+2][arow] = bv0.z; Bs[nxt][akv+3][arow] = bv0.w;
            Bs[nxt][akv+0][64+arow] = bv1.x; Bs[nxt][akv+1][64+arow] = bv1.y;
            Bs[nxt][akv+2][64+arow] = bv1.z; Bs[nxt][akv+3][64+arow] = bv1.w;
        }
        __syncthreads();
    }

    // epilogue: tanh + weighted reduction over h
    float st[8], bc[8];
    #pragma unroll
    for (int j = 0; j < 8; j++) {
        int c = n0 + tx*8 + j;
        st[j] = state[(size_t)b * H_ + c];
        bc[j] = b_c[c];
    }
    float part[4];
    #pragma unroll
    for (int i = 0; i < 4; i++) {
        float p = 0.f;
        #pragma unroll
        for (int q = 0; q < 4; q++) {
            float lo = __uint_as_float((unsigned)acc[i][q]);
            float hi = __uint_as_float((unsigned)(acc[i][q] >> 32));
            p += tanhf(lo + bc[q*2])   * st[q*2];
            p += tanhf(hi + bc[q*2+1]) * st[q*2+1];
        }
        part[i] = p;
    }
    __syncthreads();
    #pragma unroll
    for (int i = 0; i < 4; i++) red[ty*4 + i][tx] = part[i];
    __syncthreads();
    if (tid < 64) {
        float s = 0.f;
        #pragma unroll
        for (int x = 0; x < 16; x++) s += red[tid][x];
        g_scpart[(size_t)blockIdx.y * (B_ * S_) + b * S_ + s0 + tid] = s;
    }
}

__global__ void scred_kernel()
{
    int idx = blockIdx.x * 256 + threadIdx.x;   // 64*256
    int b = idx >> 8, s = idx & 255;
    float v = g_scpart[idx] + g_scpart[B_*S_ + idx]
            + g_scpart[2*B_*S_ + idx] + g_scpart[3*B_*S_ + idx];
    g_logits[(size_t)b * ML_ + V_ + s] = v;
}

// ---------------- attention scores: scores[b,s] = enc[b,s,:] . strength[b,:] -----
__global__ void __launch_bounds__(256) attn_score_kernel(const float* __restrict__ enc)
{
    __shared__ float sm[D2H];
    const int b = blockIdx.x, t = threadIdx.x;
    for (int d = t; d < D2H; d += 256) sm[d] = g_attn_strength[b * D2H + d];
    __syncthreads();
    const int warp = t >> 5, lane = t & 31;
    #pragma unroll
    for (int r = 0; r < 4; r++) {
        int s = blockIdx.y * 32 + warp + r * 8;
        const float4* row = (const float4*)(enc + ((size_t)b * S_ + s) * D2H);
        float sum = 0.f;
        for (int q = lane; q < D2H/4; q += 32) {
            float4 v = row[q];
            sum += v.x*sm[q*4] + v.y*sm[q*4+1] + v.z*sm[q*4+2] + v.w*sm[q*4+3];
        }
        #pragma unroll
        for (int o = 16; o; o >>= 1) sum += __shfl_down_sync(0xffffffffu, sum, o);
        if (lane == 0) g_scores[b * S_ + s] = sum;
    }
}

__global__ void softmax256()
{
    int b = blockIdx.x, t = threadIdx.x;
    __shared__ float sm[256];
    float v = g_scores[b * S_ + t];
    sm[t] = v; __syncthreads();
    for (int o = 128; o; o >>= 1) { if (t < o) sm[t] = fmaxf(sm[t], sm[t+o]); __syncthreads(); }
    float m = sm[0]; __syncthreads();
    float e = expf(v - m);
    sm[t] = e; __syncthreads();
    for (int o = 128; o; o >>= 1) { if (t < o) sm[t] += sm[t+o]; __syncthreads(); }
    g_scores[b * S_ + t] = e / sm[0];
}

// ---------------- context + select_reading (one pass over enc) -------------------
__global__ void __launch_bounds__(256) ctxsel_kernel(
    const float* __restrict__ enc, const int* __restrict__ seq,
    const int* __restrict__ input_idx, const float* __restrict__ ppc)
{
    const int b = blockIdx.x;
    const int t = threadIdx.x;
    const int d = blockIdx.y * 256 + t;
    __shared__ float w[S_], sw[S_];
    int idxb = input_idx[b];
    w[t]  = g_scores[b * S_ + t];
    sw[t] = (seq[b * S_ + t] == idxb) ? ppc[b * S_ + t] : 0.f;
    __syncthreads();
    const float* e = enc + (size_t)b * S_ * D2H + d;
    float ctx = 0.f, sel = 0.f;
    #pragma unroll 4
    for (int s = 0; s < S_; s++) {
        float v = e[(size_t)s * D2H];
        ctx = fmaf(w[s], v, ctx);
        sel = fmaf(sw[s], v, sel);
    }
    g_x1[b * X1W + d]      = ctx;
    g_x [b * XW + H_ + d]  = sel;    // select_reading goes to cols [512,1536)
}

__global__ void embed_kernel(const int* __restrict__ input_idx,
                             const float* __restrict__ table)
{
    int b = blockIdx.x, t = threadIdx.x;
    int idx = input_idx[b];
    if (idx >= V_) idx = 2;
    g_x1[b * X1W + D2H + t] = table[(size_t)idx * E_ + t];
}

// ---------------- GRU cell --------------------------------------------------------
__global__ void gru_kernel(const float* __restrict__ pre_state, float* __restrict__ out_state)
{
    int b = blockIdx.x, h = threadIdx.x;   // 512 threads
    float ir = g_gi[b*XW + h],        hr = g_gh[b*XW + h];
    float iz = g_gi[b*XW + H_ + h],   hz = g_gh[b*XW + H_ + h];
    float in_= g_gi[b*XW + 2*H_ + h], hn = g_gh[b*XW + 2*H_ + h];
    float r = 1.f / (1.f + expf(-(ir + hr)));
    float z = 1.f / (1.f + expf(-(iz + hz)));
    float n = tanhf(in_ + r * hn);
    float ps = pre_state[b * H_ + h];
    float st = (1.f - z) * n + z * ps;
    g_state[b * H_ + h] = st;
    out_state[b * H_ + h] = st;
}

// ---------------- big softmax over 32256, fused with final prob_g write -----------
__global__ void __launch_bounds__(1024) softmax_big(float* __restrict__ out)
{
    int b = blockIdx.x, t = threadIdx.x;
    float* row = g_logits + (size_t)b * ML_;
    float* orow = out + (size_t)b * ML_;
    __shared__ float sred[32];
    float m = -1e30f;
    for (int i = t; i < ML_; i += 1024) m = fmaxf(m, row[i]);
    #pragma unroll
    for (int o = 16; o; o >>= 1) m = fmaxf(m, __shfl_xor_sync(0xffffffffu, m, o));
    if ((t & 31) == 0) sred[t >> 5] = m;
    __syncthreads();
    if (t < 32) {
        float x = sred[t];
        #pragma unroll
        for (int o = 16; o; o >>= 1) x = fmaxf(x, __shfl_xor_sync(0xffffffffu, x, o));
        sred[t] = x;
    }
    __syncthreads();
    m = sred[0];
    __syncthreads();
    float sum = 0.f;
    for (int i = t; i < ML_; i += 1024) {
        float e = expf(row[i] - m);
        row[i] = e;
        sum += e;
    }
    #pragma unroll
    for (int o = 16; o; o >>= 1) sum += __shfl_xor_sync(0xffffffffu, sum, o);
    if ((t & 31) == 0) sred[t >> 5] = sum;
    __syncthreads();
    if (t < 32) {
        float x = sred[t];
        #pragma unroll
        for (int o = 16; o; o >>= 1) x += __shfl_xor_sync(0xffffffffu, x, o);
        sred[t] = x;
    }
    __syncthreads();
    float inv = 1.f / sred[0];
    for (int i = t; i < ML_; i += 1024) {
        float v = row[i] * inv;
        if (i < V_) {
            orow[i] = v;                 // prob_g directly to output
        } else {
            orow[i] = 0.f;               // zero pad (probc scatters on top)
            row[i]  = v;                 // normalized prob_c0 for probc_kernel
        }
    }
}

__global__ void probc_kernel(const int* __restrict__ seq, float* __restrict__ out)
{
    int b = blockIdx.x, j = threadIdx.x;
    __shared__ int   sq[S_];
    __shared__ float pc[S_];
    sq[j] = seq[b * S_ + j];
    pc[j] = g_logits[(size_t)b * ML_ + V_ + j];
    __syncthreads();
    int tok = sq[j];
    float sum = 0.f;
    bool first = true;
    for (int i = 0; i < S_; i++) {
        bool mq = (sq[i] == tok);
        if (mq) sum += pc[i];
        if (mq && i < j) first = false;
    }
    out[(size_t)B_ * ML_ + (size_t)B_ * H_ + b * S_ + j] = sum;
    if (first) out[(size_t)b * ML_ + tok] += sum;
}

// ---------------- launch -----------------------------------------------------------
extern "C" void kernel_launch(void* const* d_in, const int* in_sizes, int n_in,
                              void* d_out, int out_size)
{
    const int*   input_idx = (const int*)  d_in[0];
    const float* enc       = (const float*)d_in[1];
    const int*   seq       = (const int*)  d_in[2];
    const float* pre_state = (const float*)d_in[3];
    const float* ppc       = (const float*)d_in[4];
    const float* table     = (const float*)d_in[5];
    const float* W_aw = (const float*)d_in[6];  const float* b_aw = (const float*)d_in[7];
    const float* W_ac = (const float*)d_in[8];  const float* b_ac = (const float*)d_in[9];
    const float* W_ih = (const float*)d_in[10]; const float* b_ih = (const float*)d_in[11];
    const float* W_hh = (const float*)d_in[12]; const float* b_hh = (const float*)d_in[13];
    const float* W_o  = (const float*)d_in[14]; const float* b_o  = (const float*)d_in[15];
    const float* W_c  = (const float*)d_in[16]; const float* b_c  = (const float*)d_in[17];
    float* out = (float*)d_out;

    float *attn_strength, *x1, *x, *gi, *gh, *state, *logits;
    cudaGetSymbolAddress((void**)&attn_strength, g_attn_strength);
    cudaGetSymbolAddress((void**)&x1, g_x1);
    cudaGetSymbolAddress((void**)&x,  g_x);
    cudaGetSymbolAddress((void**)&gi, g_gi);
    cudaGetSymbolAddress((void**)&gh, g_gh);
    cudaGetSymbolAddress((void**)&state,  g_state);
    cudaGetSymbolAddress((void**)&logits, g_logits);

    // 1) embedding gather -> g_x1[:,1024:1280]
    embed_kernel<<<B_, E_>>>(input_idx, table);

    // 2) attn_strength = pre_state @ W_aw^T + b_aw   (N=1024, K=512, splitK=8)
    gemm64_kernel<<<dim3(D2H/128, 8), 256>>>(pre_state, H_, W_aw, nullptr, nullptr, 0, D2H, H_, 8);
    splitk_reduce<<<(B_*D2H + 255)/256, 256>>>(b_aw, attn_strength, D2H, D2H, 8);

    // 3) attn scores + softmax
    attn_score_kernel<<<dim3(B_, 8), 256>>>(enc);
    softmax256<<<B_, S_>>>();

    // 4) context (-> g_x1[:,0:1024]) + select_reading (-> g_x[:,512:1536])
    ctxsel_kernel<<<dim3(B_, 4), 256>>>(enc, seq, input_idx, ppc);

    // 5) attn_reading = x1 @ W_ac^T + b_ac -> g_x[:,0:512]  (N=512, K=1280, splitK=8)
    gemm64_kernel<<<dim3(H_/128, 8), 256>>>(x1, X1W, W_ac, nullptr, nullptr, 0, H_, X1W, 8);
    splitk_reduce<<<(B_*H_ + 255)/256, 256>>>(b_ac, x, XW, H_, 8);

    // 6) gi = x @ W_ih^T + b_ih  (N=1536, K=1536, splitK=8)
    gemm64_kernel<<<dim3(XW/128, 8), 256>>>(x, XW, W_ih, nullptr, nullptr, 0, XW, XW, 8);
    splitk_reduce<<<(B_*XW + 255)/256, 256>>>(b_ih, gi, XW, XW, 8);

    // 7) gh = pre_state @ W_hh^T + b_hh  (N=1536, K=512, splitK=8)
    gemm64_kernel<<<dim3(XW/128, 8), 256>>>(pre_state, H_, W_hh, nullptr, nullptr, 0, XW, H_, 8);
    splitk_reduce<<<(B_*XW + 255)/256, 256>>>(b_hh, gh, XW, XW, 8);

    // 8) GRU -> g_state and state output region
    gru_kernel<<<B_, H_>>>(pre_state, out + (size_t)B_ * ML_);

    // 9) score_g = state @ W_o^T + b_o -> logits[:, :32000]  (N=32000, K=512, splitK=2)
    gemm64_kernel<<<dim3(V_/128, 2), 256>>>(state, H_, W_o, nullptr, nullptr, 0, V_, H_, 2);
    splitk_reduce<<<(B_*V_ + 255)/256, 256>>>(b_o, logits, ML_, V_, 2);

    // 10) score_c fused (tanh(enc@W_c^T + b_c) . state) -> partials -> logits[:, 32000:]
    score_c_kernel<<<dim3(S_/64, H_/128, B_), 256>>>(enc, W_c, b_c, state);
    scred_kernel<<<B_, 256>>>();

    // 11) softmax over 32256 (fused: writes prob_g + zero pad directly to out)
    softmax_big<<<B_, 1024>>>(out);

    // 12) scatter prob_c into out; also write prob_c output region
    probc_kernel<<<B_, S_>>>(seq, out);
}

// round 5
// speedup vs baseline: 1.0001x; 1.0001x over previous
#include <cuda_runtime.h>
#include <cstddef>

// Problem constants
#define B_   64
#define S_   256
#define H_   512
#define E_   256
#define V_   32000
#define ML_  32256
#define D2H  1024          // 2*H
#define XW   1536          // 3*H (width of x, gi, gh)
#define X1W  1280          // 2*H + E

// packed fp32x2 FMA (Blackwell): c = a*b + c, elementwise on 2-lane fp32 pairs.
// "+l" ties accumulator in-place -> no MOVs around the FFMA2.
#define FMA2(c, a, b) asm("fma.rn.f32x2 %0, %1, %2, %0;" \
    : "+l"(c) : "l"(a), "l"(b))

// ---------------- scratch (device globals; no allocation allowed) ----------------
__device__ float g_attn_strength[B_ * D2H];
__device__ float g_scores[B_ * S_];          // attn scores -> weights (in place)
__device__ float g_x1[B_ * X1W];             // [context | embedding]
__device__ float g_x [B_ * XW];              // [attn_reading | select_reading]
__device__ float g_gi[B_ * XW];
__device__ float g_gh[B_ * XW];
__device__ float g_state[B_ * H_];
__device__ float g_logits[B_ * ML_];         // [score_g | score_c] -> probs (in place)
__device__ float g_part[2 * B_ * V_];        // split-K partials (largest: score_g k=2)
__device__ float g_scpart[4 * B_ * S_];      // score_c N-tile partials

// ---------------- generic fp32 GEMM: C[64,N] = A[64,K] @ B[N,K]^T (+bias) --------
// BM=64, BN=128, BK=16, 256 threads, 4x8 microtile, FFMA2 inner loop,
// double-buffered smem: ONE __syncthreads per K-tile, gmem prefetch in regs.
__global__ void __launch_bounds__(256) gemm64_kernel(
    const float* __restrict__ A, int lda,
    const float* __restrict__ Bm,
    const float* __restrict__ bias,
    float* __restrict__ C, int ldc,
    int N, int K, int kSplit)
{
    __shared__ __align__(16) float2 As2[2][16][64];   // A values duplicated (v,v)
    __shared__ __align__(16) float  Bs[2][16][128];
    const int tid  = threadIdx.x;
    const int tx   = tid & 15;
    const int ty   = tid >> 4;
    const int arow = tid >> 2;           // 0..63
    const int akv  = (tid & 3) * 4;      // 0,4,8,12
    const int n0   = blockIdx.x * 128;
    const int kLen = K / kSplit;
    const int k0   = blockIdx.y * kLen;

    const float* Ag  = A  + (size_t)arow * lda + k0 + akv;
    const float* Bg0 = Bm + (size_t)(n0 + arow) * K + k0 + akv;
    const float* Bg1 = Bm + (size_t)(n0 + 64 + arow) * K + k0 + akv;

    unsigned long long acc[4][4];        // 4 rows x 4 col-pairs, packed fp32x2
    #pragma unroll
    for (int i = 0; i < 4; i++)
        #pragma unroll
        for (int p = 0; p < 4; p++) acc[i][p] = 0ull;

    const int nTiles = kLen >> 4;

    // prologue: tile 0 -> buf 0
    {
        float4 av  = *(const float4*)(Ag);
        float4 bv0 = *(const float4*)(Bg0);
        float4 bv1 = *(const float4*)(Bg1);
        As2[0][akv+0][arow] = make_float2(av.x, av.x);
        As2[0][akv+1][arow] = make_float2(av.y, av.y);
        As2[0][akv+2][arow] = make_float2(av.z, av.z);
        As2[0][akv+3][arow] = make_float2(av.w, av.w);
        Bs[0][akv+0][arow] = bv0.x; Bs[0][akv+1][arow] = bv0.y;
        Bs[0][akv+2][arow] = bv0.z; Bs[0][akv+3][arow] = bv0.w;
        Bs[0][akv+0][64+arow] = bv1.x; Bs[0][akv+1][64+arow] = bv1.y;
        Bs[0][akv+2][64+arow] = bv1.z; Bs[0][akv+3][64+arow] = bv1.w;
    }
    __syncthreads();

    for (int t = 0; t < nTiles; t++) {
        const int cur = t & 1;
        float4 av, bv0, bv1;
        const bool more = (t + 1 < nTiles);
        if (more) {                       // prefetch next tile (overlaps compute)
            int kb = (t + 1) << 4;
            av  = *(const float4*)(Ag  + kb);
            bv0 = *(const float4*)(Bg0 + kb);
            bv1 = *(const float4*)(Bg1 + kb);
        }
        #pragma unroll
        for (int k = 0; k < 16; k++) {
            ulonglong2 a01 = *(const ulonglong2*)&As2[cur][k][ty*4];
            ulonglong2 a23 = *(const ulonglong2*)&As2[cur][k][ty*4+2];
            ulonglong2 b01 = *(const ulonglong2*)&Bs[cur][k][tx*8];
            ulonglong2 b23 = *(const ulonglong2*)&Bs[cur][k][tx*8+4];
            unsigned long long ar[4] = {a01.x, a01.y, a23.x, a23.y};
            unsigned long long br[4] = {b01.x, b01.y, b23.x, b23.y};
            #pragma unroll
            for (int i = 0; i < 4; i++)
                #pragma unroll
                for (int p = 0; p < 4; p++)
                    FMA2(acc[i][p], ar[i], br[p]);
        }
        if (more) {
            const int nxt = cur ^ 1;
            As2[nxt][akv+0][arow] = make_float2(av.x, av.x);
            As2[nxt][akv+1][arow] = make_float2(av.y, av.y);
            As2[nxt][akv+2][arow] = make_float2(av.z, av.z);
            As2[nxt][akv+3][arow] = make_float2(av.w, av.w);
            Bs[nxt][akv+0][arow] = bv0.x; Bs[nxt][akv+1][arow] = bv0.y;
            Bs[nxt][akv+2][arow] = bv0.z; Bs[nxt][akv+3][arow] = bv0.w;
            Bs[nxt][akv+0][64+arow] = bv1.x; Bs[nxt][akv+1][64+arow] = bv1.y;
            Bs[nxt][akv+2][64+arow] = bv1.z; Bs[nxt][akv+3][64+arow] = bv1.w;
        }
        __syncthreads();
    }

    if (kSplit == 1) {
        #pragma unroll
        for (int i = 0; i < 4; i++) {
            int r = ty*4 + i;
            #pragma unroll
            for (int p = 0; p < 4; p++) {
                int c = n0 + tx*8 + p*2;
                float lo = __uint_as_float((unsigned)acc[i][p]);
                float hi = __uint_as_float((unsigned)(acc[i][p] >> 32));
                if (bias) { lo += bias[c]; hi += bias[c+1]; }
                C[(size_t)r * ldc + c]     = lo;
                C[(size_t)r * ldc + c + 1] = hi;
            }
        }
    } else {
        float* P = g_part + (size_t)blockIdx.y * 64 * N;
        #pragma unroll
        for (int i = 0; i < 4; i++) {
            int r = ty*4 + i;
            #pragma unroll
            for (int p = 0; p < 4; p++) {
                int c = n0 + tx*8 + p*2;
                P[(size_t)r * N + c]     = __uint_as_float((unsigned)acc[i][p]);
                P[(size_t)r * N + c + 1] = __uint_as_float((unsigned)(acc[i][p] >> 32));
            }
        }
    }
}

// Fixed-order (deterministic) split-K reduction: C = bias + sum_z part[z]
__global__ void splitk_reduce(const float* __restrict__ bias,
                              float* __restrict__ C, int ldc, int N, int kSplit)
{
    int idx = blockIdx.x * blockDim.x + threadIdx.x;
    int total = 64 * N;
    if (idx >= total) return;
    int m = idx / N, n = idx - m * N;
    float s = bias ? bias[n] : 0.f;
    for (int z = 0; z < kSplit; z++) s += g_part[(size_t)z * total + idx];
    C[(size_t)m * ldc + n] = s;
}

// ---------------- score_c fused kernel -------------------------------------------
// For batch b, s-tile (64 rows), h-tile (128 cols):
//   F = enc_tile @ W_c^T ; partial[s] = sum_h tanh(F + b_c[h]) * state[b,h]
// Double-buffered like gemm64_kernel.
__global__ void __launch_bounds__(256) score_c_kernel(
    const float* __restrict__ enc,
    const float* __restrict__ W_c,
    const float* __restrict__ b_c,
    const float* __restrict__ state)
{
    __shared__ __align__(16) float2 As2[2][16][64];
    __shared__ __align__(16) float  Bs[2][16][128];
    __shared__ float red[64][17];
    const int tid  = threadIdx.x;
    const int tx   = tid & 15;
    const int ty   = tid >> 4;
    const int arow = tid >> 2;
    const int akv  = (tid & 3) * 4;
    const int s0   = blockIdx.x * 64;       // 0..3
    const int n0   = blockIdx.y * 128;      // 0..3
    const int b    = blockIdx.z;
    const int K    = D2H;                   // 1024

    const float* A   = enc + ((size_t)b * S_ + s0) * K;
    const float* Ag  = A   + (size_t)arow * K + akv;
    const float* Bg0 = W_c + (size_t)(n0 + arow) * K + akv;
    const float* Bg1 = W_c + (size_t)(n0 + 64 + arow) * K + akv;

    unsigned long long acc[4][4];
    #pragma unroll
    for (int i = 0; i < 4; i++)
        #pragma unroll
        for (int p = 0; p < 4; p++) acc[i][p] = 0ull;

    const int nTiles = K >> 4;   // 64

    {
        float4 av  = *(const float4*)(Ag);
        float4 bv0 = *(const float4*)(Bg0);
        float4 bv1 = *(const float4*)(Bg1);
        As2[0][akv+0][arow] = make_float2(av.x, av.x);
        As2[0][akv+1][arow] = make_float2(av.y, av.y);
        As2[0][akv+2][arow] = make_float2(av.z, av.z);
        As2[0][akv+3][arow] = make_float2(av.w, av.w);
        Bs[0][akv+0][arow] = bv0.x; Bs[0][akv+1][arow] = bv0.y;
        Bs[0][akv+2][arow] = bv0.z; Bs[0][akv+3][arow] = bv0.w;
        Bs[0][akv+0][64+arow] = bv1.x; Bs[0][akv+1][64+arow] = bv1.y;
        Bs[0][akv+2][64+arow] = bv1.z; Bs[0][akv+3][64+arow] = bv1.w;
    }
    __syncthreads();

    for (int t = 0; t < nTiles; t++) {
        const int cur = t & 1;
        float4 av, bv0, bv1;
        const bool more = (t + 1 < nTiles);
        if (more) {
            int kb = (t + 1) << 4;
            av  = *(const float4*)(Ag  + kb);
            bv0 = *(const float4*)(Bg0 + kb);
            bv1 = *(const float4*)(Bg1 + kb);
        }
        #pragma unroll
        for (int k = 0; k < 16; k++) {
            ulonglong2 a01 = *(const ulonglong2*)&As2[cur][k][ty*4];
            ulonglong2 a23 = *(const ulonglong2*)&As2[cur][k][ty*4+2];
            ulonglong2 b01 = *(const ulonglong2*)&Bs[cur][k][tx*8];
            ulonglong2 b23 = *(const ulonglong2*)&Bs[cur][k][tx*8+4];
            unsigned long long ar[4] = {a01.x, a01.y, a23.x, a23.y};
            unsigned long long br[4] = {b01.x, b01.y, b23.x, b23.y};
            #pragma unroll
            for (int i = 0; i < 4; i++)
                #pragma unroll
                for (int p = 0; p < 4; p++)
                    FMA2(acc[i][p], ar[i], br[p]);
        }
        if (more) {
            const int nxt = cur ^ 1;
            As2[nxt][akv+0][arow] = make_float2(av.x, av.x);
            As2[nxt][akv+1][arow] = make_float2(av.y, av.y);
            As2[nxt][akv+2][arow] = make_float2(av.z, av.z);
            As2[nxt][akv+3][arow] = make_float2(av.w, av.w);
            Bs[nxt][akv+0][arow] = bv0.x; Bs[nxt][akv+1][arow] = bv0.y;
            Bs[nxt][akv+2][arow] = bv0.z; Bs[nxt][akv+3][arow] = bv0.w;
            Bs[nxt][akv+0][64+arow] = bv1.x; Bs[nxt][akv+1][64+arow] = bv1.y;
            Bs[nxt][akv+2][64+arow] = bv1.z; Bs[nxt][akv+3][64+arow] = bv1.w;
        }
        __syncthreads();
    }

    // epilogue: tanh + weighted reduction over h
    float st[8], bc[8];
    #pragma unroll
    for (int j = 0; j < 8; j++) {
        int c = n0 + tx*8 + j;
        st[j] = state[(size_t)b * H_ + c];
        bc[j] = b_c[c];
    }
    float part[4];
    #pragma unroll
    for (int i = 0; i < 4; i++) {
        float p = 0.f;
        #pragma unroll
        for (int q = 0; q < 4; q++) {
            float lo = __uint_as_float((unsigned)acc[i][q]);
            float hi = __uint_as_float((unsigned)(acc[i][q] >> 32));
            p += tanhf(lo + bc[q*2])   * st[q*2];
            p += tanhf(hi + bc[q*2+1]) * st[q*2+1];
        }
        part[i] = p;
    }
    __syncthreads();
    #pragma unroll
    for (int i = 0; i < 4; i++) red[ty*4 + i][tx] = part[i];
    __syncthreads();
    if (tid < 64) {
        float s = 0.f;
        #pragma unroll
        for (int x = 0; x < 16; x++) s += red[tid][x];
        g_scpart[(size_t)blockIdx.y * (B_ * S_) + b * S_ + s0 + tid] = s;
    }
}

__global__ void scred_kernel()
{
    int idx = blockIdx.x * 256 + threadIdx.x;   // 64*256
    int b = idx >> 8, s = idx & 255;
    float v = g_scpart[idx] + g_scpart[B_*S_ + idx]
            + g_scpart[2*B_*S_ + idx] + g_scpart[3*B_*S_ + idx];
    g_logits[(size_t)b * ML_ + V_ + s] = v;
}

// ---------------- attention scores: scores[b,s] = enc[b,s,:] . strength[b,:] -----
__global__ void __launch_bounds__(256) attn_score_kernel(const float* __restrict__ enc)
{
    __shared__ float sm[D2H];
    const int b = blockIdx.x, t = threadIdx.x;
    for (int d = t; d < D2H; d += 256) sm[d] = g_attn_strength[b * D2H + d];
    __syncthreads();
    const int warp = t >> 5, lane = t & 31;
    #pragma unroll
    for (int r = 0; r < 4; r++) {
        int s = blockIdx.y * 32 + warp + r * 8;
        const float4* row = (const float4*)(enc + ((size_t)b * S_ + s) * D2H);
        float sum = 0.f;
        for (int q = lane; q < D2H/4; q += 32) {
            float4 v = row[q];
            sum += v.x*sm[q*4] + v.y*sm[q*4+1] + v.z*sm[q*4+2] + v.w*sm[q*4+3];
        }
        #pragma unroll
        for (int o = 16; o; o >>= 1) sum += __shfl_down_sync(0xffffffffu, sum, o);
        if (lane == 0) g_scores[b * S_ + s] = sum;
    }
}

__global__ void softmax256()
{
    int b = blockIdx.x, t = threadIdx.x;
    __shared__ float sm[256];
    float v = g_scores[b * S_ + t];
    sm[t] = v; __syncthreads();
    for (int o = 128; o; o >>= 1) { if (t < o) sm[t] = fmaxf(sm[t], sm[t+o]); __syncthreads(); }
    float m = sm[0]; __syncthreads();
    float e = expf(v - m);
    sm[t] = e; __syncthreads();
    for (int o = 128; o; o >>= 1) { if (t < o) sm[t] += sm[t+o]; __syncthreads(); }
    g_scores[b * S_ + t] = e / sm[0];
}

// ---------------- context + select_reading (one pass over enc) -------------------
__global__ void __launch_bounds__(256) ctxsel_kernel(
    const float* __restrict__ enc, const int* __restrict__ seq,
    const int* __restrict__ input_idx, const float* __restrict__ ppc)
{
    const int b = blockIdx.x;
    const int t = threadIdx.x;
    const int d = blockIdx.y * 256 + t;
    __shared__ float w[S_], sw[S_];
    int idxb = input_idx[b];
    w[t]  = g_scores[b * S_ + t];
    sw[t] = (seq[b * S_ + t] == idxb) ? ppc[b * S_ + t] : 0.f;
    __syncthreads();
    const float* e = enc + (size_t)b * S_ * D2H + d;
    float ctx = 0.f, sel = 0.f;
    #pragma unroll 4
    for (int s = 0; s < S_; s++) {
        float v = e[(size_t)s * D2H];
        ctx = fmaf(w[s], v, ctx);
        sel = fmaf(sw[s], v, sel);
    }
    g_x1[b * X1W + d]      = ctx;
    g_x [b * XW + H_ + d]  = sel;    // select_reading goes to cols [512,1536)
}

__global__ void embed_kernel(const int* __restrict__ input_idx,
                             const float* __restrict__ table)
{
    int b = blockIdx.x, t = threadIdx.x;
    int idx = input_idx[b];
    if (idx >= V_) idx = 2;
    g_x1[b * X1W + D2H + t] = table[(size_t)idx * E_ + t];
}

// ---------------- GRU cell --------------------------------------------------------
__global__ void gru_kernel(const float* __restrict__ pre_state, float* __restrict__ out_state)
{
    int b = blockIdx.x, h = threadIdx.x;   // 512 threads
    float ir = g_gi[b*XW + h],        hr = g_gh[b*XW + h];
    float iz = g_gi[b*XW + H_ + h],   hz = g_gh[b*XW + H_ + h];
    float in_= g_gi[b*XW + 2*H_ + h], hn = g_gh[b*XW + 2*H_ + h];
    float r = 1.f / (1.f + expf(-(ir + hr)));
    float z = 1.f / (1.f + expf(-(iz + hz)));
    float n = tanhf(in_ + r * hn);
    float ps = pre_state[b * H_ + h];
    float st = (1.f - z) * n + z * ps;
    g_state[b * H_ + h] = st;
    out_state[b * H_ + h] = st;
}

// ---------------- big softmax over 32256, fused with final prob_g write -----------
__global__ void __launch_bounds__(1024) softmax_big(float* __restrict__ out)
{
    int b = blockIdx.x, t = threadIdx.x;
    float* row = g_logits + (size_t)b * ML_;
    float* orow = out + (size_t)b * ML_;
    __shared__ float sred[32];
    float m = -1e30f;
    for (int i = t; i < ML_; i += 1024) m = fmaxf(m, row[i]);
    #pragma unroll
    for (int o = 16; o; o >>= 1) m = fmaxf(m, __shfl_xor_sync(0xffffffffu, m, o));
    if ((t & 31) == 0) sred[t >> 5] = m;
    __syncthreads();
    if (t < 32) {
        float x = sred[t];
        #pragma unroll
        for (int o = 16; o; o >>= 1) x = fmaxf(x, __shfl_xor_sync(0xffffffffu, x, o));
        sred[t] = x;
    }
    __syncthreads();
    m = sred[0];
    __syncthreads();
    float sum = 0.f;
    for (int i = t; i < ML_; i += 1024) {
        float e = expf(row[i] - m);
        row[i] = e;
        sum += e;
    }
    #pragma unroll
    for (int o = 16; o; o >>= 1) sum += __shfl_xor_sync(0xffffffffu, sum, o);
    if ((t & 31) == 0) sred[t >> 5] = sum;
    __syncthreads();
    if (t < 32) {
        float x = sred[t];
        #pragma unroll
        for (int o = 16; o; o >>= 1) x += __shfl_xor_sync(0xffffffffu, x, o);
        sred[t] = x;
    }
    __syncthreads();
    float inv = 1.f / sred[0];
    for (int i = t; i < ML_; i += 1024) {
        float v = row[i] * inv;
        if (i < V_) {
            orow[i] = v;                 // prob_g directly to output
        } else {
            orow[i] = 0.f;               // zero pad (probc scatters on top)
            row[i]  = v;                 // normalized prob_c0 for probc_kernel
        }
    }
}

__global__ void probc_kernel(const int* __restrict__ seq, float* __restrict__ out)
{
    int b = blockIdx.x, j = threadIdx.x;
    __shared__ int   sq[S_];
    __shared__ float pc[S_];
    sq[j] = seq[b * S_ + j];
    pc[j] = g_logits[(size_t)b * ML_ + V_ + j];
    __syncthreads();
    int tok = sq[j];
    float sum = 0.f;
    bool first = true;
    for (int i = 0; i < S_; i++) {
        bool mq = (sq[i] == tok);
        if (mq) sum += pc[i];
        if (mq && i < j) first = false;
    }
    out[(size_t)B_ * ML_ + (size_t)B_ * H_ + b * S_ + j] = sum;
    if (first) out[(size_t)b * ML_ + tok] += sum;
}

// ---------------- launch -----------------------------------------------------------
extern "C" void kernel_launch(void* const* d_in, const int* in_sizes, int n_in,
                              void* d_out, int out_size)
{
    const int*   input_idx = (const int*)  d_in[0];
    const float* enc       = (const float*)d_in[1];
    const int*   seq       = (const int*)  d_in[2];
    const float* pre_state = (const float*)d_in[3];
    const float* ppc       = (const float*)d_in[4];
    const float* table     = (const float*)d_in[5];
    const float* W_aw = (const float*)d_in[6];  const float* b_aw = (const float*)d_in[7];
    const float* W_ac = (const float*)d_in[8];  const float* b_ac = (const float*)d_in[9];
    const float* W_ih = (const float*)d_in[10]; const float* b_ih = (const float*)d_in[11];
    const float* W_hh = (const float*)d_in[12]; const float* b_hh = (const float*)d_in[13];
    const float* W_o  = (const float*)d_in[14]; const float* b_o  = (const float*)d_in[15];
    const float* W_c  = (const float*)d_in[16]; const float* b_c  = (const float*)d_in[17];
    float* out = (float*)d_out;

    float *attn_strength, *x1, *x, *gi, *gh, *state, *logits;
    cudaGetSymbolAddress((void**)&attn_strength, g_attn_strength);
    cudaGetSymbolAddress((void**)&x1, g_x1);
    cudaGetSymbolAddress((void**)&x,  g_x);
    cudaGetSymbolAddress((void**)&gi, g_gi);
    cudaGetSymbolAddress((void**)&gh, g_gh);
    cudaGetSymbolAddress((void**)&state,  g_state);
    cudaGetSymbolAddress((void**)&logits, g_logits);

    // 1) embedding gather -> g_x1[:,1024:1280]
    embed_kernel<<<B_, E_>>>(input_idx, table);

    // 2) attn_strength = pre_state @ W_aw^T + b_aw   (N=1024, K=512, splitK=8)
    gemm64_kernel<<<dim3(D2H/128, 8), 256>>>(pre_state, H_, W_aw, nullptr, nullptr, 0, D2H, H_, 8);
    splitk_reduce<<<(B_*D2H + 255)/256, 256>>>(b_aw, attn_strength, D2H, D2H, 8);

    // 3) attn scores + softmax
    attn_score_kernel<<<dim3(B_, 8), 256>>>(enc);
    softmax256<<<B_, S_>>>();

    // 4) context (-> g_x1[:,0:1024]) + select_reading (-> g_x[:,512:1536])
    ctxsel_kernel<<<dim3(B_, 4), 256>>>(enc, seq, input_idx, ppc);

    // 5) attn_reading = x1 @ W_ac^T + b_ac -> g_x[:,0:512]  (N=512, K=1280, splitK=8)
    gemm64_kernel<<<dim3(H_/128, 8), 256>>>(x1, X1W, W_ac, nullptr, nullptr, 0, H_, X1W, 8);
    splitk_reduce<<<(B_*H_ + 255)/256, 256>>>(b_ac, x, XW, H_, 8);

    // 6) gi = x @ W_ih^T + b_ih  (N=1536, K=1536, splitK=8)
    gemm64_kernel<<<dim3(XW/128, 8), 256>>>(x, XW, W_ih, nullptr, nullptr, 0, XW, XW, 8);
    splitk_reduce<<<(B_*XW + 255)/256, 256>>>(b_ih, gi, XW, XW, 8);

    // 7) gh = pre_state @ W_hh^T + b_hh  (N=1536, K=512, splitK=8)
    gemm64_kernel<<<dim3(XW/128, 8), 256>>>(pre_state, H_, W_hh, nullptr, nullptr, 0, XW, H_, 8);
    splitk_reduce<<<(B_*XW + 255)/256, 256>>>(b_hh, gh, XW, XW, 8);

    // 8) GRU -> g_state and state output region
    gru_kernel<<<B_, H_>>>(pre_state, out + (size_t)B_ * ML_);

    // 9) score_g = state @ W_o^T + b_o -> logits[:, :32000]  (N=32000, K=512, splitK=2)
    gemm64_kernel<<<dim3(V_/128, 2), 256>>>(state, H_, W_o, nullptr, nullptr, 0, V_, H_, 2);
    splitk_reduce<<<(B_*V_ + 255)/256, 256>>>(b_o, logits, ML_, V_, 2);

    // 10) score_c fused (tanh(enc@W_c^T + b_c) . state) -> partials -> logits[:, 32000:]
    score_c_kernel<<<dim3(S_/64, H_/128, B_), 256>>>(enc, W_c, b_c, state);
    scred_kernel<<<B_, 256>>>();

    // 11) softmax over 32256 (fused: writes prob_g + zero pad directly to out)
    softmax_big<<<B_, 1024>>>(out);

    // 12) scatter prob_c into out; also write prob_c output region
    probc_kernel<<<B_, S_>>>(seq, out);
}

// round 7
// speedup vs baseline: 1.9039x; 1.9038x over previous
#include <cuda_runtime.h>
#include <cuda_bf16.h>
#include <cstdint>
#include <cstddef>

#define B_   64
#define S_   256
#define H_   512
#define E_   256
#define V_   32000
#define ML_  32256
#define D2H  1024
#define XW   1536
#define X1W  1280

#define FMA2(c, a, b) asm("fma.rn.f32x2 %0, %1, %2, %0;" : "+l"(c) : "l"(a), "l"(b))

// warp-level bf16 HMMA, fp32 accumulate (sm_80+ baseline feature, valid on sm_103)
#define MMA_BF16(d, a, b) \
    asm volatile("mma.sync.aligned.m16n8k16.row.col.f32.bf16.bf16.f32 " \
        "{%0,%1,%2,%3}, {%4,%5,%6,%7}, {%8,%9}, {%0,%1,%2,%3};" \
        : "+f"((d)[0]), "+f"((d)[1]), "+f"((d)[2]), "+f"((d)[3]) \
        : "r"((a)[0]), "r"((a)[1]), "r"((a)[2]), "r"((a)[3]), "r"((b)[0]), "r"((b)[1]))

// ---- scratch ----
__device__ float g_attn_strength[B_ * D2H];
__device__ float g_scores[B_ * S_];
__device__ float g_x1[B_ * X1W];
__device__ float g_x [B_ * XW];
__device__ float g_gi[B_ * XW];
__device__ float g_gh[B_ * XW];
__device__ float g_state[B_ * H_];
__device__ float g_logits[B_ * ML_];
__device__ float g_part[2 * B_ * V_];
__device__ float g_scpart[4 * B_ * S_];

// ---- fp32 GEMM (FFMA2, double-buffered) C[64,N] = A[64,K] @ B[N,K]^T ----
__global__ void __launch_bounds__(256) gemm64_kernel(
    const float* __restrict__ A, int lda, const float* __restrict__ Bm,
    const float* __restrict__ bias, float* __restrict__ C, int ldc,
    int N, int K, int kSplit)
{
    __shared__ __align__(16) float2 As2[2][16][64];
    __shared__ __align__(16) float  Bs[2][16][128];
    const int tid = threadIdx.x, tx = tid & 15, ty = tid >> 4;
    const int arow = tid >> 2, akv = (tid & 3) * 4;
    const int n0 = blockIdx.x * 128;
    const int kLen = K / kSplit, k0 = blockIdx.y * kLen;
    const float* Ag  = A  + (size_t)arow * lda + k0 + akv;
    const float* Bg0 = Bm + (size_t)(n0 + arow) * K + k0 + akv;
    const float* Bg1 = Bm + (size_t)(n0 + 64 + arow) * K + k0 + akv;
    unsigned long long acc[4][4];
    #pragma unroll
    for (int i = 0; i < 4; i++)
        #pragma unroll
        for (int p = 0; p < 4; p++) acc[i][p] = 0ull;
    const int nTiles = kLen >> 4;
    {
        float4 av = *(const float4*)(Ag), bv0 = *(const float4*)(Bg0), bv1 = *(const float4*)(Bg1);
        As2[0][akv+0][arow] = make_float2(av.x, av.x); As2[0][akv+1][arow] = make_float2(av.y, av.y);
        As2[0][akv+2][arow] = make_float2(av.z, av.z); As2[0][akv+3][arow] = make_float2(av.w, av.w);
        Bs[0][akv+0][arow] = bv0.x; Bs[0][akv+1][arow] = bv0.y; Bs[0][akv+2][arow] = bv0.z; Bs[0][akv+3][arow] = bv0.w;
        Bs[0][akv+0][64+arow] = bv1.x; Bs[0][akv+1][64+arow] = bv1.y; Bs[0][akv+2][64+arow] = bv1.z; Bs[0][akv+3][64+arow] = bv1.w;
    }
    __syncthreads();
    for (int t = 0; t < nTiles; t++) {
        const int cur = t & 1;
        float4 av, bv0, bv1;
        const bool more = (t + 1 < nTiles);
        if (more) {
            int kb = (t + 1) << 4;
            av = *(const float4*)(Ag + kb); bv0 = *(const float4*)(Bg0 + kb); bv1 = *(const float4*)(Bg1 + kb);
        }
        #pragma unroll
        for (int k = 0; k < 16; k++) {
            ulonglong2 a01 = *(const ulonglong2*)&As2[cur][k][ty*4];
            ulonglong2 a23 = *(const ulonglong2*)&As2[cur][k][ty*4+2];
            ulonglong2 b01 = *(const ulonglong2*)&Bs[cur][k][tx*8];
            ulonglong2 b23 = *(const ulonglong2*)&Bs[cur][k][tx*8+4];
            unsigned long long ar[4] = {a01.x, a01.y, a23.x, a23.y};
            unsigned long long br[4] = {b01.x, b01.y, b23.x, b23.y};
            #pragma unroll
            for (int i = 0; i < 4; i++)
                #pragma unroll
                for (int p = 0; p < 4; p++) FMA2(acc[i][p], ar[i], br[p]);
        }
        if (more) {
            const int nxt = cur ^ 1;
            As2[nxt][akv+0][arow] = make_float2(av.x, av.x); As2[nxt][akv+1][arow] = make_float2(av.y, av.y);
            As2[nxt][akv+2][arow] = make_float2(av.z, av.z); As2[nxt][akv+3][arow] = make_float2(av.w, av.w);
            Bs[nxt][akv+0][arow] = bv0.x; Bs[nxt][akv+1][arow] = bv0.y; Bs[nxt][akv+2][arow] = bv0.z; Bs[nxt][akv+3][arow] = bv0.w;
            Bs[nxt][akv+0][64+arow] = bv1.x; Bs[nxt][akv+1][64+arow] = bv1.y; Bs[nxt][akv+2][64+arow] = bv1.z; Bs[nxt][akv+3][64+arow] = bv1.w;
        }
        __syncthreads();
    }
    if (kSplit == 1) {
        #pragma unroll
        for (int i = 0; i < 4; i++) {
            int r = ty*4 + i;
            #pragma unroll
            for (int p = 0; p < 4; p++) {
                int c = n0 + tx*8 + p*2;
                float lo = __uint_as_float((unsigned)acc[i][p]);
                float hi = __uint_as_float((unsigned)(acc[i][p] >> 32));
                if (bias) { lo += bias[c]; hi += bias[c+1]; }
                C[(size_t)r * ldc + c] = lo; C[(size_t)r * ldc + c + 1] = hi;
            }
        }
    } else {
        float* P = g_part + (size_t)blockIdx.y * 64 * N;
        #pragma unroll
        for (int i = 0; i < 4; i++) {
            int r = ty*4 + i;
            #pragma unroll
            for (int p = 0; p < 4; p++) {
                int c = n0 + tx*8 + p*2;
                P[(size_t)r * N + c]     = __uint_as_float((unsigned)acc[i][p]);
                P[(size_t)r * N + c + 1] = __uint_as_float((unsigned)(acc[i][p] >> 32));
            }
        }
    }
}

__global__ void splitk_reduce(const float* __restrict__ bias,
                              float* __restrict__ C, int ldc, int N, int kSplit)
{
    int idx = blockIdx.x * blockDim.x + threadIdx.x;
    int total = 64 * N;
    if (idx >= total) return;
    int m = idx / N, n = idx - m * N;
    float s = bias ? bias[n] : 0.f;
    for (int z = 0; z < kSplit; z++) s += g_part[(size_t)z * total + idx];
    C[(size_t)m * ldc + n] = s;
}

// ---- score_c via warp-level bf16 HMMA (3-split, fp32 accumulate) ----
// Block: 128 s-rows x 128 W_c-rows, 8 warps (2x4), warp tile 64x32.
// K=1024 in 32 chunks of 32. smem rows padded to 72B (conflict-free frags).
#define SC_STRIDE 72

__global__ void __launch_bounds__(256) score_c_mma(
    const float* __restrict__ enc, const float* __restrict__ W_c,
    const float* __restrict__ b_c, const float* __restrict__ state)
{
    __shared__ __align__(16) uint8_t Ahi[128 * SC_STRIDE];
    __shared__ __align__(16) uint8_t Alo[128 * SC_STRIDE];
    __shared__ __align__(16) uint8_t Bhi[128 * SC_STRIDE];
    __shared__ __align__(16) uint8_t Blo[128 * SC_STRIDE];
    __shared__ float red[128][5];

    const int tid  = threadIdx.x;
    const int wid  = tid >> 5, lane = tid & 31;
    const int g    = lane >> 2, tg = lane & 3;     // groupID, threadID_in_group
    const int wm   = wid >> 2,  wn = wid & 3;      // warp 64-row x 32-col tile
    const int s0   = blockIdx.x * 128, n0 = blockIdx.y * 128, b = blockIdx.z;

    // loader mapping: row = tid>>1 (0..127), half = tid&1 -> 16 k-values
    const int lrow = tid >> 1, lhalf = tid & 1;
    const float* Asrc = enc + ((size_t)(b * S_ + s0 + lrow)) * D2H + lhalf * 16;
    const float* Bsrc = W_c + ((size_t)(n0 + lrow)) * D2H + lhalf * 16;
    uint8_t* AdH = Ahi + lrow * SC_STRIDE + lhalf * 32;
    uint8_t* AdL = Alo + lrow * SC_STRIDE + lhalf * 32;
    uint8_t* BdH = Bhi + lrow * SC_STRIDE + lhalf * 32;
    uint8_t* BdL = Blo + lrow * SC_STRIDE + lhalf * 32;

    float acc[4][4][4];
    #pragma unroll
    for (int mi = 0; mi < 4; mi++)
        #pragma unroll
        for (int ni = 0; ni < 4; ni++)
            #pragma unroll
            for (int q = 0; q < 4; q++) acc[mi][ni][q] = 0.f;

    for (int kc = 0; kc < 32; kc++) {
        // load fp32 chunk, split to bf16 hi/lo, store to padded smem
        #pragma unroll
        for (int i = 0; i < 4; i++) {
            float4 a = *(const float4*)(Asrc + kc * 32 + i * 4);
            __nv_bfloat162 h01 = make_bfloat162(__float2bfloat16(a.x), __float2bfloat16(a.y));
            __nv_bfloat162 h23 = make_bfloat162(__float2bfloat16(a.z), __float2bfloat16(a.w));
            __nv_bfloat162 l01 = make_bfloat162(
                __float2bfloat16(a.x - __bfloat162float(h01.x)),
                __float2bfloat16(a.y - __bfloat162float(h01.y)));
            __nv_bfloat162 l23 = make_bfloat162(
                __float2bfloat16(a.z - __bfloat162float(h23.x)),
                __float2bfloat16(a.w - __bfloat162float(h23.y)));
            *(uint2*)(AdH + i * 8) = make_uint2(*(uint32_t*)&h01, *(uint32_t*)&h23);
            *(uint2*)(AdL + i * 8) = make_uint2(*(uint32_t*)&l01, *(uint32_t*)&l23);

            float4 w = *(const float4*)(Bsrc + kc * 32 + i * 4);
            __nv_bfloat162 wh01 = make_bfloat162(__float2bfloat16(w.x), __float2bfloat16(w.y));
            __nv_bfloat162 wh23 = make_bfloat162(__float2bfloat16(w.z), __float2bfloat16(w.w));
            __nv_bfloat162 wl01 = make_bfloat162(
                __float2bfloat16(w.x - __bfloat162float(wh01.x)),
                __float2bfloat16(w.y - __bfloat162float(wh01.y)));
            __nv_bfloat162 wl23 = make_bfloat162(
                __float2bfloat16(w.z - __bfloat162float(wh23.x)),
                __float2bfloat16(w.w - __bfloat162float(wh23.y)));
            *(uint2*)(BdH + i * 8) = make_uint2(*(uint32_t*)&wh01, *(uint32_t*)&wh23);
            *(uint2*)(BdL + i * 8) = make_uint2(*(uint32_t*)&wl01, *(uint32_t*)&wl23);
        }
        __syncthreads();

        #pragma unroll
        for (int ks = 0; ks < 2; ks++) {           // 2 k16 steps per chunk
            const int ko = ks * 32 + tg * 4;       // byte offset for k-pair 2*tg
            uint32_t ah[4][4], al[4][4];
            #pragma unroll
            for (int mi = 0; mi < 4; mi++) {
                const uint8_t* p = Ahi + (size_t)(wm * 64 + mi * 16 + g) * SC_STRIDE + ko;
                const uint8_t* q = Alo + (size_t)(wm * 64 + mi * 16 + g) * SC_STRIDE + ko;
                ah[mi][0] = *(const uint32_t*)(p);
                ah[mi][1] = *(const uint32_t*)(p + 8 * SC_STRIDE);
                ah[mi][2] = *(const uint32_t*)(p + 16);
                ah[mi][3] = *(const uint32_t*)(p + 8 * SC_STRIDE + 16);
                al[mi][0] = *(const uint32_t*)(q);
                al[mi][1] = *(const uint32_t*)(q + 8 * SC_STRIDE);
                al[mi][2] = *(const uint32_t*)(q + 16);
                al[mi][3] = *(const uint32_t*)(q + 8 * SC_STRIDE + 16);
            }
            #pragma unroll
            for (int ni = 0; ni < 4; ni++) {
                const uint8_t* p = Bhi + (size_t)(wn * 32 + ni * 8 + g) * SC_STRIDE + ko;
                const uint8_t* q = Blo + (size_t)(wn * 32 + ni * 8 + g) * SC_STRIDE + ko;
                uint32_t bh[2] = { *(const uint32_t*)(p), *(const uint32_t*)(p + 16) };
                uint32_t bl[2] = { *(const uint32_t*)(q), *(const uint32_t*)(q + 16) };
                #pragma unroll
                for (int mi = 0; mi < 4; mi++) {
                    MMA_BF16(acc[mi][ni], ah[mi], bh);
                    MMA_BF16(acc[mi][ni], ah[mi], bl);
                    MMA_BF16(acc[mi][ni], al[mi], bh);
                }
            }
        }
        __syncthreads();
    }

    // epilogue: tanh(acc + b_c) * state, reduce over n
    float pr[4][2];
    #pragma unroll
    for (int mi = 0; mi < 4; mi++) { pr[mi][0] = 0.f; pr[mi][1] = 0.f; }
    #pragma unroll
    for (int ni = 0; ni < 4; ni++) {
        int c0 = n0 + wn * 32 + ni * 8 + 2 * tg;
        float bc0 = b_c[c0], bc1 = b_c[c0 + 1];
        float st0 = state[(size_t)b * H_ + c0], st1 = state[(size_t)b * H_ + c0 + 1];
        #pragma unroll
        for (int mi = 0; mi < 4; mi++) {
            pr[mi][0] += tanhf(acc[mi][ni][0] + bc0) * st0 + tanhf(acc[mi][ni][1] + bc1) * st1;
            pr[mi][1] += tanhf(acc[mi][ni][2] + bc0) * st0 + tanhf(acc[mi][ni][3] + bc1) * st1;
        }
    }
    #pragma unroll
    for (int mi = 0; mi < 4; mi++) {
        #pragma unroll
        for (int h = 0; h < 2; h++) {
            float v = pr[mi][h];
            v += __shfl_xor_sync(0xffffffffu, v, 1);
            v += __shfl_xor_sync(0xffffffffu, v, 2);
            if (tg == 0) red[wm * 64 + mi * 16 + h * 8 + g][wn] = v;
        }
    }
    __syncthreads();
    if (tid < 128) {
        float s = red[tid][0] + red[tid][1] + red[tid][2] + red[tid][3];
        g_scpart[(size_t)blockIdx.y * (B_ * S_) + b * S_ + s0 + tid] = s;
    }
}

__global__ void scred_kernel()
{
    int idx = blockIdx.x * 256 + threadIdx.x;
    int b = idx >> 8, s = idx & 255;
    float v = g_scpart[idx] + g_scpart[B_*S_ + idx]
            + g_scpart[2*B_*S_ + idx] + g_scpart[3*B_*S_ + idx];
    g_logits[(size_t)b * ML_ + V_ + s] = v;
}

// ---- attention scores ----
__global__ void __launch_bounds__(256) attn_score_kernel(const float* __restrict__ enc)
{
    __shared__ float sm[D2H];
    const int b = blockIdx.x, t = threadIdx.x;
    for (int d = t; d < D2H; d += 256) sm[d] = g_attn_strength[b * D2H + d];
    __syncthreads();
    const int warp = t >> 5, lane = t & 31;
    #pragma unroll
    for (int r = 0; r < 4; r++) {
        int s = blockIdx.y * 32 + warp + r * 8;
        const float4* row = (const float4*)(enc + ((size_t)b * S_ + s) * D2H);
        float sum = 0.f;
        for (int q = lane; q < D2H/4; q += 32) {
            float4 v = row[q];
            sum += v.x*sm[q*4] + v.y*sm[q*4+1] + v.z*sm[q*4+2] + v.w*sm[q*4+3];
        }
        #pragma unroll
        for (int o = 16; o; o >>= 1) sum += __shfl_down_sync(0xffffffffu, sum, o);
        if (lane == 0) g_scores[b * S_ + s] = sum;
    }
}

__global__ void softmax256()
{
    int b = blockIdx.x, t = threadIdx.x;
    __shared__ float sm[256];
    float v = g_scores[b * S_ + t];
    sm[t] = v; __syncthreads();
    for (int o = 128; o; o >>= 1) { if (t < o) sm[t] = fmaxf(sm[t], sm[t+o]); __syncthreads(); }
    float m = sm[0]; __syncthreads();
    float e = expf(v - m);
    sm[t] = e; __syncthreads();
    for (int o = 128; o; o >>= 1) { if (t < o) sm[t] += sm[t+o]; __syncthreads(); }
    g_scores[b * S_ + t] = e / sm[0];
}

__global__ void __launch_bounds__(256) ctxsel_kernel(
    const float* __restrict__ enc, const int* __restrict__ seq,
    const int* __restrict__ input_idx, const float* __restrict__ ppc)
{
    const int b = blockIdx.x, t = threadIdx.x;
    const int d = blockIdx.y * 256 + t;
    __shared__ float w[S_], sw[S_];
    int idxb = input_idx[b];
    w[t]  = g_scores[b * S_ + t];
    sw[t] = (seq[b * S_ + t] == idxb) ? ppc[b * S_ + t] : 0.f;
    __syncthreads();
    const float* e = enc + (size_t)b * S_ * D2H + d;
    float ctx = 0.f, sel = 0.f;
    #pragma unroll 4
    for (int s = 0; s < S_; s++) {
        float v = e[(size_t)s * D2H];
        ctx = fmaf(w[s], v, ctx);
        sel = fmaf(sw[s], v, sel);
    }
    g_x1[b * X1W + d]     = ctx;
    g_x [b * XW + H_ + d] = sel;
}

__global__ void embed_kernel(const int* __restrict__ input_idx,
                             const float* __restrict__ table)
{
    int b = blockIdx.x, t = threadIdx.x;
    int idx = input_idx[b];
    if (idx >= V_) idx = 2;
    g_x1[b * X1W + D2H + t] = table[(size_t)idx * E_ + t];
}

__global__ void gru_kernel(const float* __restrict__ pre_state, float* __restrict__ out_state)
{
    int b = blockIdx.x, h = threadIdx.x;
    float ir = g_gi[b*XW + h],        hr = g_gh[b*XW + h];
    float iz = g_gi[b*XW + H_ + h],   hz = g_gh[b*XW + H_ + h];
    float in_= g_gi[b*XW + 2*H_ + h], hn = g_gh[b*XW + 2*H_ + h];
    float r = 1.f / (1.f + expf(-(ir + hr)));
    float z = 1.f / (1.f + expf(-(iz + hz)));
    float n = tanhf(in_ + r * hn);
    float ps = pre_state[b * H_ + h];
    float st = (1.f - z) * n + z * ps;
    g_state[b * H_ + h] = st;
    out_state[b * H_ + h] = st;
}

__global__ void __launch_bounds__(1024) softmax_big(float* __restrict__ out)
{
    int b = blockIdx.x, t = threadIdx.x;
    float* row = g_logits + (size_t)b * ML_;
    float* orow = out + (size_t)b * ML_;
    __shared__ float sred[32];
    float m = -1e30f;
    for (int i = t; i < ML_; i += 1024) m = fmaxf(m, row[i]);
    #pragma unroll
    for (int o = 16; o; o >>= 1) m = fmaxf(m, __shfl_xor_sync(0xffffffffu, m, o));
    if ((t & 31) == 0) sred[t >> 5] = m;
    __syncthreads();
    if (t < 32) {
        float x = sred[t];
        #pragma unroll
        for (int o = 16; o; o >>= 1) x = fmaxf(x, __shfl_xor_sync(0xffffffffu, x, o));
        sred[t] = x;
    }
    __syncthreads();
    m = sred[0];
    __syncthreads();
    float sum = 0.f;
    for (int i = t; i < ML_; i += 1024) {
        float e = expf(row[i] - m);
        row[i] = e;
        sum += e;
    }
    #pragma unroll
    for (int o = 16; o; o >>= 1) sum += __shfl_xor_sync(0xffffffffu, sum, o);
    if ((t & 31) == 0) sred[t >> 5] = sum;
    __syncthreads();
    if (t < 32) {
        float x = sred[t];
        #pragma unroll
        for (int o = 16; o; o >>= 1) x += __shfl_xor_sync(0xffffffffu, x, o);
        sred[t] = x;
    }
    __syncthreads();
    float inv = 1.f / sred[0];
    for (int i = t; i < ML_; i += 1024) {
        float v = row[i] * inv;
        if (i < V_) orow[i] = v;
        else { orow[i] = 0.f; row[i] = v; }
    }
}

__global__ void probc_kernel(const int* __restrict__ seq, float* __restrict__ out)
{
    int b = blockIdx.x, j = threadIdx.x;
    __shared__ int   sq[S_];
    __shared__ float pc[S_];
    sq[j] = seq[b * S_ + j];
    pc[j] = g_logits[(size_t)b * ML_ + V_ + j];
    __syncthreads();
    int tok = sq[j];
    float sum = 0.f;
    bool first = true;
    for (int i = 0; i < S_; i++) {
        bool mq = (sq[i] == tok);
        if (mq) sum += pc[i];
        if (mq && i < j) first = false;
    }
    out[(size_t)B_ * ML_ + (size_t)B_ * H_ + b * S_ + j] = sum;
    if (first) out[(size_t)b * ML_ + tok] += sum;
}

// ---- launch ----
extern "C" void kernel_launch(void* const* d_in, const int* in_sizes, int n_in,
                              void* d_out, int out_size)
{
    const int*   input_idx = (const int*)  d_in[0];
    const float* enc       = (const float*)d_in[1];
    const int*   seq       = (const int*)  d_in[2];
    const float* pre_state = (const float*)d_in[3];
    const float* ppc       = (const float*)d_in[4];
    const float* table     = (const float*)d_in[5];
    const float* W_aw = (const float*)d_in[6];  const float* b_aw = (const float*)d_in[7];
    const float* W_ac = (const float*)d_in[8];  const float* b_ac = (const float*)d_in[9];
    const float* W_ih = (const float*)d_in[10]; const float* b_ih = (const float*)d_in[11];
    const float* W_hh = (const float*)d_in[12]; const float* b_hh = (const float*)d_in[13];
    const float* W_o  = (const float*)d_in[14]; const float* b_o  = (const float*)d_in[15];
    const float* W_c  = (const float*)d_in[16]; const float* b_c  = (const float*)d_in[17];
    float* out = (float*)d_out;

    float *attn_strength, *x1, *x, *gi, *gh, *state, *logits;
    cudaGetSymbolAddress((void**)&attn_strength, g_attn_strength);
    cudaGetSymbolAddress((void**)&x1, g_x1);
    cudaGetSymbolAddress((void**)&x,  g_x);
    cudaGetSymbolAddress((void**)&gi, g_gi);
    cudaGetSymbolAddress((void**)&gh, g_gh);
    cudaGetSymbolAddress((void**)&state,  g_state);
    cudaGetSymbolAddress((void**)&logits, g_logits);

    embed_kernel<<<B_, E_>>>(input_idx, table);

    gemm64_kernel<<<dim3(D2H/128, 8), 256>>>(pre_state, H_, W_aw, nullptr, nullptr, 0, D2H, H_, 8);
    splitk_reduce<<<(B_*D2H + 255)/256, 256>>>(b_aw, attn_strength, D2H, D2H, 8);

    attn_score_kernel<<<dim3(B_, 8), 256>>>(enc);
    softmax256<<<B_, S_>>>();

    ctxsel_kernel<<<dim3(B_, 4), 256>>>(enc, seq, input_idx, ppc);

    gemm64_kernel<<<dim3(H_/128, 8), 256>>>(x1, X1W, W_ac, nullptr, nullptr, 0, H_, X1W, 8);
    splitk_reduce<<<(B_*H_ + 255)/256, 256>>>(b_ac, x, XW, H_, 8);

    gemm64_kernel<<<dim3(XW/128, 8), 256>>>(x, XW, W_ih, nullptr, nullptr, 0, XW, XW, 8);
    splitk_reduce<<<(B_*XW + 255)/256, 256>>>(b_ih, gi, XW, XW, 8);

    gemm64_kernel<<<dim3(XW/128, 8), 256>>>(pre_state, H_, W_hh, nullptr, nullptr, 0, XW, H_, 8);
    splitk_reduce<<<(B_*XW + 255)/256, 256>>>(b_hh, gh, XW, XW, 8);

    gru_kernel<<<B_, H_>>>(pre_state, out + (size_t)B_ * ML_);

    gemm64_kernel<<<dim3(V_/128, 2), 256>>>(state, H_, W_o, nullptr, nullptr, 0, V_, H_, 2);
    splitk_reduce<<<(B_*V_ + 255)/256, 256>>>(b_o, logits, ML_, V_, 2);

    score_c_mma<<<dim3(S_/128, H_/128, B_), 256>>>(enc, W_c, b_c, state);
    scred_kernel<<<B_, 256>>>();

    softmax_big<<<B_, 1024>>>(out);
    probc_kernel<<<B_, S_>>>(seq, out);
}

// round 8
// speedup vs baseline: 2.3607x; 1.2399x over previous
#include <cuda_runtime.h>
#include <cuda_bf16.h>
#include <cstdint>
#include <cstddef>

#define B_   64
#define S_   256
#define H_   512
#define E_   256
#define V_   32000
#define ML_  32256
#define D2H  1024
#define XW   1536
#define X1W  1280

// warp-level bf16 HMMA, fp32 accumulate (baseline PTX feature on sm_103)
#define MMA_BF16(d, a, b) \
    asm volatile("mma.sync.aligned.m16n8k16.row.col.f32.bf16.bf16.f32 " \
        "{%0,%1,%2,%3}, {%4,%5,%6,%7}, {%8,%9}, {%0,%1,%2,%3};" \
        : "+f"((d)[0]), "+f"((d)[1]), "+f"((d)[2]), "+f"((d)[3]) \
        : "r"((a)[0]), "r"((a)[1]), "r"((a)[2]), "r"((a)[3]), "r"((b)[0]), "r"((b)[1]))

// fp32 -> bf16 hi/lo split of a float4, packed as 2x u32 each
__device__ __forceinline__ void split4(float4 v, uint2& hi, uint2& lo) {
    __nv_bfloat162 h01 = make_bfloat162(__float2bfloat16(v.x), __float2bfloat16(v.y));
    __nv_bfloat162 h23 = make_bfloat162(__float2bfloat16(v.z), __float2bfloat16(v.w));
    __nv_bfloat162 l01 = make_bfloat162(
        __float2bfloat16(v.x - __bfloat162float(h01.x)),
        __float2bfloat16(v.y - __bfloat162float(h01.y)));
    __nv_bfloat162 l23 = make_bfloat162(
        __float2bfloat16(v.z - __bfloat162float(h23.x)),
        __float2bfloat16(v.w - __bfloat162float(h23.y)));
    hi = make_uint2(*(uint32_t*)&h01, *(uint32_t*)&h23);
    lo = make_uint2(*(uint32_t*)&l01, *(uint32_t*)&l23);
}

// ---- scratch ----
__device__ float g_attn_strength[B_ * D2H];
__device__ float g_scores[B_ * S_];
__device__ float g_x1[B_ * X1W];
__device__ float g_x [B_ * XW];
__device__ float g_gi[B_ * XW];
__device__ float g_gh[B_ * XW];
__device__ float g_state[B_ * H_];
__device__ float g_logits[B_ * ML_];
__device__ float g_part[8 * B_ * XW > 2 * B_ * V_ ? 8 * B_ * XW : 2 * B_ * V_];
__device__ float g_scpart[4 * B_ * S_];

// ---- generic HMMA GEMM: C[64,N] = A[64,K] @ B[N,K]^T (+bias), bf16 3-split ----
// Block: 64 rows x 128 cols. 8 warps (2x4), warp tile 32x32. K chunks of 32.
#define HS 72
__global__ void __launch_bounds__(256) hmma64_kernel(
    const float* __restrict__ A, int lda, const float* __restrict__ Bm,
    const float* __restrict__ bias, float* __restrict__ C, int ldc,
    int N, int K, int kSplit)
{
    __shared__ __align__(16) uint8_t AhiS[64 * HS], AloS[64 * HS];
    __shared__ __align__(16) uint8_t BhiS[128 * HS], BloS[128 * HS];
    const int tid = threadIdx.x, wid = tid >> 5, lane = tid & 31;
    const int g = lane >> 2, tg = lane & 3;
    const int wm = wid >> 2, wn = wid & 3;
    const int n0 = blockIdx.x * 128;
    const int kLen = K / kSplit, k0 = blockIdx.y * kLen;
    const int nch = kLen >> 5;

    const int lrow = tid >> 1, lhalf = tid & 1;
    const float* Bsrc = Bm + (size_t)(n0 + lrow) * K + k0 + lhalf * 16;
    uint8_t* BdH = BhiS + lrow * HS + lhalf * 32;
    uint8_t* BdL = BloS + lrow * HS + lhalf * 32;
    const float* Asrc = A + (size_t)lrow * lda + k0 + lhalf * 16;   // valid when lrow<64
    uint8_t* AdH = AhiS + lrow * HS + lhalf * 32;
    uint8_t* AdL = AloS + lrow * HS + lhalf * 32;

    float acc[2][4][4];
    #pragma unroll
    for (int mi = 0; mi < 2; mi++)
        #pragma unroll
        for (int ni = 0; ni < 4; ni++)
            #pragma unroll
            for (int q = 0; q < 4; q++) acc[mi][ni][q] = 0.f;

    for (int kc = 0; kc < nch; kc++) {
        #pragma unroll
        for (int i = 0; i < 4; i++) {
            uint2 hi, lo;
            split4(*(const float4*)(Bsrc + kc * 32 + i * 4), hi, lo);
            *(uint2*)(BdH + i * 8) = hi;
            *(uint2*)(BdL + i * 8) = lo;
            if (tid < 128) {
                split4(*(const float4*)(Asrc + kc * 32 + i * 4), hi, lo);
                *(uint2*)(AdH + i * 8) = hi;
                *(uint2*)(AdL + i * 8) = lo;
            }
        }
        __syncthreads();
        #pragma unroll
        for (int ks = 0; ks < 2; ks++) {
            const int ko = ks * 32 + tg * 4;
            uint32_t ah[2][4], al[2][4];
            #pragma unroll
            for (int mi = 0; mi < 2; mi++) {
                const uint8_t* p = AhiS + (size_t)(wm * 32 + mi * 16 + g) * HS + ko;
                const uint8_t* q = AloS + (size_t)(wm * 32 + mi * 16 + g) * HS + ko;
                ah[mi][0] = *(const uint32_t*)(p);
                ah[mi][1] = *(const uint32_t*)(p + 8 * HS);
                ah[mi][2] = *(const uint32_t*)(p + 16);
                ah[mi][3] = *(const uint32_t*)(p + 8 * HS + 16);
                al[mi][0] = *(const uint32_t*)(q);
                al[mi][1] = *(const uint32_t*)(q + 8 * HS);
                al[mi][2] = *(const uint32_t*)(q + 16);
                al[mi][3] = *(const uint32_t*)(q + 8 * HS + 16);
            }
            #pragma unroll
            for (int ni = 0; ni < 4; ni++) {
                const uint8_t* p = BhiS + (size_t)(wn * 32 + ni * 8 + g) * HS + ko;
                const uint8_t* q = BloS + (size_t)(wn * 32 + ni * 8 + g) * HS + ko;
                uint32_t bh[2] = { *(const uint32_t*)(p), *(const uint32_t*)(p + 16) };
                uint32_t bl[2] = { *(const uint32_t*)(q), *(const uint32_t*)(q + 16) };
                #pragma unroll
                for (int mi = 0; mi < 2; mi++) {
                    MMA_BF16(acc[mi][ni], ah[mi], bh);
                    MMA_BF16(acc[mi][ni], ah[mi], bl);
                    MMA_BF16(acc[mi][ni], al[mi], bh);
                }
            }
        }
        __syncthreads();
    }

    if (kSplit == 1) {
        #pragma unroll
        for (int mi = 0; mi < 2; mi++) {
            int r = wm * 32 + mi * 16 + g;
            #pragma unroll
            for (int ni = 0; ni < 4; ni++) {
                int c = n0 + wn * 32 + ni * 8 + 2 * tg;
                float b0 = bias ? bias[c] : 0.f, b1 = bias ? bias[c+1] : 0.f;
                C[(size_t)r * ldc + c]           = acc[mi][ni][0] + b0;
                C[(size_t)r * ldc + c + 1]       = acc[mi][ni][1] + b1;
                C[(size_t)(r + 8) * ldc + c]     = acc[mi][ni][2] + b0;
                C[(size_t)(r + 8) * ldc + c + 1] = acc[mi][ni][3] + b1;
            }
        }
    } else {
        float* P = g_part + (size_t)blockIdx.y * 64 * N;
        #pragma unroll
        for (int mi = 0; mi < 2; mi++) {
            int r = wm * 32 + mi * 16 + g;
            #pragma unroll
            for (int ni = 0; ni < 4; ni++) {
                int c = n0 + wn * 32 + ni * 8 + 2 * tg;
                P[(size_t)r * N + c]           = acc[mi][ni][0];
                P[(size_t)r * N + c + 1]       = acc[mi][ni][1];
                P[(size_t)(r + 8) * N + c]     = acc[mi][ni][2];
                P[(size_t)(r + 8) * N + c + 1] = acc[mi][ni][3];
            }
        }
    }
}

__global__ void splitk_reduce(const float* __restrict__ bias,
                              float* __restrict__ C, int ldc, int N, int kSplit)
{
    int idx = blockIdx.x * blockDim.x + threadIdx.x;
    int total = 64 * N;
    if (idx >= total) return;
    int m = idx / N, n = idx - m * N;
    float s = bias ? bias[n] : 0.f;
    for (int z = 0; z < kSplit; z++) s += g_part[(size_t)z * total + idx];
    C[(size_t)m * ldc + n] = s;
}

// ---- score_c via warp-level bf16 HMMA (validated R7 kernel, unchanged) ----
#define SC_STRIDE 72
__global__ void __launch_bounds__(256) score_c_mma(
    const float* __restrict__ enc, const float* __restrict__ W_c,
    const float* __restrict__ b_c, const float* __restrict__ state)
{
    __shared__ __align__(16) uint8_t Ahi[128 * SC_STRIDE];
    __shared__ __align__(16) uint8_t Alo[128 * SC_STRIDE];
    __shared__ __align__(16) uint8_t Bhi[128 * SC_STRIDE];
    __shared__ __align__(16) uint8_t Blo[128 * SC_STRIDE];
    __shared__ float red[128][5];

    const int tid  = threadIdx.x;
    const int wid  = tid >> 5, lane = tid & 31;
    const int g    = lane >> 2, tg = lane & 3;
    const int wm   = wid >> 2,  wn = wid & 3;
    const int s0   = blockIdx.x * 128, n0 = blockIdx.y * 128, b = blockIdx.z;

    const int lrow = tid >> 1, lhalf = tid & 1;
    const float* Asrc = enc + ((size_t)(b * S_ + s0 + lrow)) * D2H + lhalf * 16;
    const float* Bsrc = W_c + ((size_t)(n0 + lrow)) * D2H + lhalf * 16;
    uint8_t* AdH = Ahi + lrow * SC_STRIDE + lhalf * 32;
    uint8_t* AdL = Alo + lrow * SC_STRIDE + lhalf * 32;
    uint8_t* BdH = Bhi + lrow * SC_STRIDE + lhalf * 32;
    uint8_t* BdL = Blo + lrow * SC_STRIDE + lhalf * 32;

    float acc[4][4][4];
    #pragma unroll
    for (int mi = 0; mi < 4; mi++)
        #pragma unroll
        for (int ni = 0; ni < 4; ni++)
            #pragma unroll
            for (int q = 0; q < 4; q++) acc[mi][ni][q] = 0.f;

    for (int kc = 0; kc < 32; kc++) {
        #pragma unroll
        for (int i = 0; i < 4; i++) {
            uint2 hi, lo;
            split4(*(const float4*)(Asrc + kc * 32 + i * 4), hi, lo);
            *(uint2*)(AdH + i * 8) = hi;
            *(uint2*)(AdL + i * 8) = lo;
            split4(*(const float4*)(Bsrc + kc * 32 + i * 4), hi, lo);
            *(uint2*)(BdH + i * 8) = hi;
            *(uint2*)(BdL + i * 8) = lo;
        }
        __syncthreads();

        #pragma unroll
        for (int ks = 0; ks < 2; ks++) {
            const int ko = ks * 32 + tg * 4;
            uint32_t ah[4][4], al[4][4];
            #pragma unroll
            for (int mi = 0; mi < 4; mi++) {
                const uint8_t* p = Ahi + (size_t)(wm * 64 + mi * 16 + g) * SC_STRIDE + ko;
                const uint8_t* q = Alo + (size_t)(wm * 64 + mi * 16 + g) * SC_STRIDE + ko;
                ah[mi][0] = *(const uint32_t*)(p);
                ah[mi][1] = *(const uint32_t*)(p + 8 * SC_STRIDE);
                ah[mi][2] = *(const uint32_t*)(p + 16);
                ah[mi][3] = *(const uint32_t*)(p + 8 * SC_STRIDE + 16);
                al[mi][0] = *(const uint32_t*)(q);
                al[mi][1] = *(const uint32_t*)(q + 8 * SC_STRIDE);
                al[mi][2] = *(const uint32_t*)(q + 16);
                al[mi][3] = *(const uint32_t*)(q + 8 * SC_STRIDE + 16);
            }
            #pragma unroll
            for (int ni = 0; ni < 4; ni++) {
                const uint8_t* p = Bhi + (size_t)(wn * 32 + ni * 8 + g) * SC_STRIDE + ko;
                const uint8_t* q = Blo + (size_t)(wn * 32 + ni * 8 + g) * SC_STRIDE + ko;
                uint32_t bh[2] = { *(const uint32_t*)(p), *(const uint32_t*)(p + 16) };
                uint32_t bl[2] = { *(const uint32_t*)(q), *(const uint32_t*)(q + 16) };
                #pragma unroll
                for (int mi = 0; mi < 4; mi++) {
                    MMA_BF16(acc[mi][ni], ah[mi], bh);
                    MMA_BF16(acc[mi][ni], ah[mi], bl);
                    MMA_BF16(acc[mi][ni], al[mi], bh);
                }
            }
        }
        __syncthreads();
    }

    float pr[4][2];
    #pragma unroll
    for (int mi = 0; mi < 4; mi++) { pr[mi][0] = 0.f; pr[mi][1] = 0.f; }
    #pragma unroll
    for (int ni = 0; ni < 4; ni++) {
        int c0 = n0 + wn * 32 + ni * 8 + 2 * tg;
        float bc0 = b_c[c0], bc1 = b_c[c0 + 1];
        float st0 = state[(size_t)b * H_ + c0], st1 = state[(size_t)b * H_ + c0 + 1];
        #pragma unroll
        for (int mi = 0; mi < 4; mi++) {
            pr[mi][0] += tanhf(acc[mi][ni][0] + bc0) * st0 + tanhf(acc[mi][ni][1] + bc1) * st1;
            pr[mi][1] += tanhf(acc[mi][ni][2] + bc0) * st0 + tanhf(acc[mi][ni][3] + bc1) * st1;
        }
    }
    #pragma unroll
    for (int mi = 0; mi < 4; mi++) {
        #pragma unroll
        for (int h = 0; h < 2; h++) {
            float v = pr[mi][h];
            v += __shfl_xor_sync(0xffffffffu, v, 1);
            v += __shfl_xor_sync(0xffffffffu, v, 2);
            if (tg == 0) red[wm * 64 + mi * 16 + h * 8 + g][wn] = v;
        }
    }
    __syncthreads();
    if (tid < 128) {
        float s = red[tid][0] + red[tid][1] + red[tid][2] + red[tid][3];
        g_scpart[(size_t)blockIdx.y * (B_ * S_) + b * S_ + s0 + tid] = s;
    }
}

__global__ void scred_kernel()
{
    int idx = blockIdx.x * 256 + threadIdx.x;
    int b = idx >> 8, s = idx & 255;
    float v = g_scpart[idx] + g_scpart[B_*S_ + idx]
            + g_scpart[2*B_*S_ + idx] + g_scpart[3*B_*S_ + idx];
    g_logits[(size_t)b * ML_ + V_ + s] = v;
}

// ---- attention scores ----
__global__ void __launch_bounds__(256) attn_score_kernel(const float* __restrict__ enc)
{
    __shared__ float sm[D2H];
    const int b = blockIdx.x, t = threadIdx.x;
    for (int d = t; d < D2H; d += 256) sm[d] = g_attn_strength[b * D2H + d];
    __syncthreads();
    const int warp = t >> 5, lane = t & 31;
    #pragma unroll
    for (int r = 0; r < 4; r++) {
        int s = blockIdx.y * 32 + warp + r * 8;
        const float4* row = (const float4*)(enc + ((size_t)b * S_ + s) * D2H);
        float sum = 0.f;
        for (int q = lane; q < D2H/4; q += 32) {
            float4 v = row[q];
            sum += v.x*sm[q*4] + v.y*sm[q*4+1] + v.z*sm[q*4+2] + v.w*sm[q*4+3];
        }
        #pragma unroll
        for (int o = 16; o; o >>= 1) sum += __shfl_down_sync(0xffffffffu, sum, o);
        if (lane == 0) g_scores[b * S_ + s] = sum;
    }
}

__global__ void softmax256()
{
    int b = blockIdx.x, t = threadIdx.x;
    __shared__ float sm[256];
    float v = g_scores[b * S_ + t];
    sm[t] = v; __syncthreads();
    for (int o = 128; o; o >>= 1) { if (t < o) sm[t] = fmaxf(sm[t], sm[t+o]); __syncthreads(); }
    float m = sm[0]; __syncthreads();
    float e = expf(v - m);
    sm[t] = e; __syncthreads();
    for (int o = 128; o; o >>= 1) { if (t < o) sm[t] += sm[t+o]; __syncthreads(); }
    g_scores[b * S_ + t] = e / sm[0];
}

__global__ void __launch_bounds__(256) ctxsel_kernel(
    const float* __restrict__ enc, const int* __restrict__ seq,
    const int* __restrict__ input_idx, const float* __restrict__ ppc)
{
    const int b = blockIdx.x, t = threadIdx.x;
    const int d = blockIdx.y * 256 + t;
    __shared__ float w[S_], sw[S_];
    int idxb = input_idx[b];
    w[t]  = g_scores[b * S_ + t];
    sw[t] = (seq[b * S_ + t] == idxb) ? ppc[b * S_ + t] : 0.f;
    __syncthreads();
    const float* e = enc + (size_t)b * S_ * D2H + d;
    float ctx = 0.f, sel = 0.f;
    #pragma unroll 4
    for (int s = 0; s < S_; s++) {
        float v = e[(size_t)s * D2H];
        ctx = fmaf(w[s], v, ctx);
        sel = fmaf(sw[s], v, sel);
    }
    g_x1[b * X1W + d]     = ctx;
    g_x [b * XW + H_ + d] = sel;
}

__global__ void embed_kernel(const int* __restrict__ input_idx,
                             const float* __restrict__ table)
{
    int b = blockIdx.x, t = threadIdx.x;
    int idx = input_idx[b];
    if (idx >= V_) idx = 2;
    g_x1[b * X1W + D2H + t] = table[(size_t)idx * E_ + t];
}

__global__ void gru_kernel(const float* __restrict__ pre_state, float* __restrict__ out_state)
{
    int b = blockIdx.x, h = threadIdx.x;
    float ir = g_gi[b*XW + h],        hr = g_gh[b*XW + h];
    float iz = g_gi[b*XW + H_ + h],   hz = g_gh[b*XW + H_ + h];
    float in_= g_gi[b*XW + 2*H_ + h], hn = g_gh[b*XW + 2*H_ + h];
    float r = 1.f / (1.f + expf(-(ir + hr)));
    float z = 1.f / (1.f + expf(-(iz + hz)));
    float n = tanhf(in_ + r * hn);
    float ps = pre_state[b * H_ + h];
    float st = (1.f - z) * n + z * ps;
    g_state[b * H_ + h] = st;
    out_state[b * H_ + h] = st;
}

__global__ void __launch_bounds__(1024) softmax_big(float* __restrict__ out)
{
    int b = blockIdx.x, t = threadIdx.x;
    float* row = g_logits + (size_t)b * ML_;
    float* orow = out + (size_t)b * ML_;
    __shared__ float sred[32];
    float m = -1e30f;
    for (int i = t; i < ML_; i += 1024) m = fmaxf(m, row[i]);
    #pragma unroll
    for (int o = 16; o; o >>= 1) m = fmaxf(m, __shfl_xor_sync(0xffffffffu, m, o));
    if ((t & 31) == 0) sred[t >> 5] = m;
    __syncthreads();
    if (t < 32) {
        float x = sred[t];
        #pragma unroll
        for (int o = 16; o; o >>= 1) x = fmaxf(x, __shfl_xor_sync(0xffffffffu, x, o));
        sred[t] = x;
    }
    __syncthreads();
    m = sred[0];
    __syncthreads();
    float sum = 0.f;
    for (int i = t; i < ML_; i += 1024) {
        float e = expf(row[i] - m);
        row[i] = e;
        sum += e;
    }
    #pragma unroll
    for (int o = 16; o; o >>= 1) sum += __shfl_xor_sync(0xffffffffu, sum, o);
    if ((t & 31) == 0) sred[t >> 5] = sum;
    __syncthreads();
    if (t < 32) {
        float x = sred[t];
        #pragma unroll
        for (int o = 16; o; o >>= 1) x += __shfl_xor_sync(0xffffffffu, x, o);
        sred[t] = x;
    }
    __syncthreads();
    float inv = 1.f / sred[0];
    for (int i = t; i < ML_; i += 1024) {
        float v = row[i] * inv;
        if (i < V_) orow[i] = v;
        else { orow[i] = 0.f; row[i] = v; }
    }
}

__global__ void probc_kernel(const int* __restrict__ seq, float* __restrict__ out)
{
    int b = blockIdx.x, j = threadIdx.x;
    __shared__ int   sq[S_];
    __shared__ float pc[S_];
    sq[j] = seq[b * S_ + j];
    pc[j] = g_logits[(size_t)b * ML_ + V_ + j];
    __syncthreads();
    int tok = sq[j];
    float sum = 0.f;
    bool first = true;
    for (int i = 0; i < S_; i++) {
        bool mq = (sq[i] == tok);
        if (mq) sum += pc[i];
        if (mq && i < j) first = false;
    }
    out[(size_t)B_ * ML_ + (size_t)B_ * H_ + b * S_ + j] = sum;
    if (first) out[(size_t)b * ML_ + tok] += sum;
}

// ---- launch ----
extern "C" void kernel_launch(void* const* d_in, const int* in_sizes, int n_in,
                              void* d_out, int out_size)
{
    const int*   input_idx = (const int*)  d_in[0];
    const float* enc       = (const float*)d_in[1];
    const int*   seq       = (const int*)  d_in[2];
    const float* pre_state = (const float*)d_in[3];
    const float* ppc       = (const float*)d_in[4];
    const float* table     = (const float*)d_in[5];
    const float* W_aw = (const float*)d_in[6];  const float* b_aw = (const float*)d_in[7];
    const float* W_ac = (const float*)d_in[8];  const float* b_ac = (const float*)d_in[9];
    const float* W_ih = (const float*)d_in[10]; const float* b_ih = (const float*)d_in[11];
    const float* W_hh = (const float*)d_in[12]; const float* b_hh = (const float*)d_in[13];
    const float* W_o  = (const float*)d_in[14]; const float* b_o  = (const float*)d_in[15];
    const float* W_c  = (const float*)d_in[16]; const float* b_c  = (const float*)d_in[17];
    float* out = (float*)d_out;

    float *attn_strength, *x1, *x, *gi, *gh, *state, *logits;
    cudaGetSymbolAddress((void**)&attn_strength, g_attn_strength);
    cudaGetSymbolAddress((void**)&x1, g_x1);
    cudaGetSymbolAddress((void**)&x,  g_x);
    cudaGetSymbolAddress((void**)&gi, g_gi);
    cudaGetSymbolAddress((void**)&gh, g_gh);
    cudaGetSymbolAddress((void**)&state,  g_state);
    cudaGetSymbolAddress((void**)&logits, g_logits);

    embed_kernel<<<B_, E_>>>(input_idx, table);

    // attn_strength = pre_state @ W_aw^T + b_aw   (N=1024, K=512, splitK=8)
    hmma64_kernel<<<dim3(D2H/128, 8), 256>>>(pre_state, H_, W_aw, nullptr, nullptr, 0, D2H, H_, 8);
    splitk_reduce<<<(B_*D2H + 255)/256, 256>>>(b_aw, attn_strength, D2H, D2H, 8);

    attn_score_kernel<<<dim3(B_, 8), 256>>>(enc);
    softmax256<<<B_, S_>>>();

    ctxsel_kernel<<<dim3(B_, 4), 256>>>(enc, seq, input_idx, ppc);

    // attn_reading (N=512, K=1280, splitK=8: kLen=160 -> 5 chunks)
    hmma64_kernel<<<dim3(H_/128, 8), 256>>>(x1, X1W, W_ac, nullptr, nullptr, 0, H_, X1W, 8);
    splitk_reduce<<<(B_*H_ + 255)/256, 256>>>(b_ac, x, XW, H_, 8);

    // gi (N=1536, K=1536, splitK=8: 6 chunks)
    hmma64_kernel<<<dim3(XW/128, 8), 256>>>(x, XW, W_ih, nullptr, nullptr, 0, XW, XW, 8);
    splitk_reduce<<<(B_*XW + 255)/256, 256>>>(b_ih, gi, XW, XW, 8);

    // gh (N=1536, K=512, splitK=8: 2 chunks)
    hmma64_kernel<<<dim3(XW/128, 8), 256>>>(pre_state, H_, W_hh, nullptr, nullptr, 0, XW, H_, 8);
    splitk_reduce<<<(B_*XW + 255)/256, 256>>>(b_hh, gh, XW, XW, 8);

    gru_kernel<<<B_, H_>>>(pre_state, out + (size_t)B_ * ML_);

    // score_g (N=32000, K=512, direct with bias)
    hmma64_kernel<<<dim3(V_/128, 1), 256>>>(state, H_, W_o, b_o, logits, ML_, V_, H_, 1);

    score_c_mma<<<dim3(S_/128, H_/128, B_), 256>>>(enc, W_c, b_c, state);
    scred_kernel<<<B_, 256>>>();

    softmax_big<<<B_, 1024>>>(out);
    probc_kernel<<<B_, S_>>>(seq, out);
}

// round 10
// speedup vs baseline: 2.5881x; 1.0963x over previous
#include <cuda_runtime.h>
#include <cuda_bf16.h>
#include <cstdint>
#include <cstddef>

#define B_   64
#define S_   256
#define H_   512
#define E_   256
#define V_   32000
#define ML_  32256
#define D2H  1024
#define XW   1536
#define X1W  1280

// warp-level bf16 HMMA, fp32 accumulate (baseline PTX feature on sm_103)
#define MMA_BF16(d, a, b) \
    asm volatile("mma.sync.aligned.m16n8k16.row.col.f32.bf16.bf16.f32 " \
        "{%0,%1,%2,%3}, {%4,%5,%6,%7}, {%8,%9}, {%0,%1,%2,%3};" \
        : "+f"((d)[0]), "+f"((d)[1]), "+f"((d)[2]), "+f"((d)[3]) \
        : "r"((a)[0]), "r"((a)[1]), "r"((a)[2]), "r"((a)[3]), "r"((b)[0]), "r"((b)[1]))

__device__ __forceinline__ void split4(float4 v, uint2& hi, uint2& lo) {
    __nv_bfloat162 h01 = make_bfloat162(__float2bfloat16(v.x), __float2bfloat16(v.y));
    __nv_bfloat162 h23 = make_bfloat162(__float2bfloat16(v.z), __float2bfloat16(v.w));
    __nv_bfloat162 l01 = make_bfloat162(
        __float2bfloat16(v.x - __bfloat162float(h01.x)),
        __float2bfloat16(v.y - __bfloat162float(h01.y)));
    __nv_bfloat162 l23 = make_bfloat162(
        __float2bfloat16(v.z - __bfloat162float(h23.x)),
        __float2bfloat16(v.w - __bfloat162float(h23.y)));
    hi = make_uint2(*(uint32_t*)&h01, *(uint32_t*)&h23);
    lo = make_uint2(*(uint32_t*)&l01, *(uint32_t*)&l23);
}

// ---- scratch ----
__device__ float g_x1[B_ * X1W];
__device__ float g_x [B_ * XW];
__device__ float g_state[B_ * H_];
__device__ float g_logits[B_ * ML_];
__device__ float g_part [8 * B_ * XW];
__device__ float g_part2[8 * B_ * XW];
__device__ float g_scpart[4 * B_ * S_];

// ---- generic HMMA GEMM body: C[64,N] = A[64,K] @ B[N,K]^T (+bias), bf16 3-split
// Block tile: 64 rows x 128 cols. 8 warps (2x4), warp tile 32x32. K chunks of 32.
#define HS 72
__device__ __forceinline__ void hmma64_body(
    const float* __restrict__ A, int lda, const float* __restrict__ Bm,
    const float* __restrict__ bias, float* __restrict__ C, int ldc,
    float* __restrict__ P, int N, int K, int kSplit,
    int bx, int by, uint8_t* __restrict__ smem)
{
    uint8_t* AhiS = smem;
    uint8_t* AloS = smem + 64 * HS;
    uint8_t* BhiS = smem + 128 * HS;
    uint8_t* BloS = smem + 256 * HS;

    const int tid = threadIdx.x, wid = tid >> 5, lane = tid & 31;
    const int g = lane >> 2, tg = lane & 3;
    const int wm = wid >> 2, wn = wid & 3;
    const int n0 = bx * 128;
    const int kLen = K / kSplit, k0 = by * kLen;
    const int nch = kLen >> 5;

    const int lrow = tid >> 1, lhalf = tid & 1;
    const float* Bsrc = Bm + (size_t)(n0 + lrow) * K + k0 + lhalf * 16;
    uint8_t* BdH = BhiS + lrow * HS + lhalf * 32;
    uint8_t* BdL = BloS + lrow * HS + lhalf * 32;
    const float* Asrc = A + (size_t)lrow * lda + k0 + lhalf * 16;
    uint8_t* AdH = AhiS + lrow * HS + lhalf * 32;
    uint8_t* AdL = AloS + lrow * HS + lhalf * 32;

    float acc[2][4][4];
    #pragma unroll
    for (int mi = 0; mi < 2; mi++)
        #pragma unroll
        for (int ni = 0; ni < 4; ni++)
            #pragma unroll
            for (int q = 0; q < 4; q++) acc[mi][ni][q] = 0.f;

    for (int kc = 0; kc < nch; kc++) {
        #pragma unroll
        for (int i = 0; i < 4; i++) {
            uint2 hi, lo;
            split4(*(const float4*)(Bsrc + kc * 32 + i * 4), hi, lo);
            *(uint2*)(BdH + i * 8) = hi;
            *(uint2*)(BdL + i * 8) = lo;
            if (tid < 128) {
                split4(*(const float4*)(Asrc + kc * 32 + i * 4), hi, lo);
                *(uint2*)(AdH + i * 8) = hi;
                *(uint2*)(AdL + i * 8) = lo;
            }
        }
        __syncthreads();
        #pragma unroll
        for (int ks = 0; ks < 2; ks++) {
            const int ko = ks * 32 + tg * 4;
            uint32_t ah[2][4], al[2][4];
            #pragma unroll
            for (int mi = 0; mi < 2; mi++) {
                const uint8_t* p = AhiS + (size_t)(wm * 32 + mi * 16 + g) * HS + ko;
                const uint8_t* q = AloS + (size_t)(wm * 32 + mi * 16 + g) * HS + ko;
                ah[mi][0] = *(const uint32_t*)(p);
                ah[mi][1] = *(const uint32_t*)(p + 8 * HS);
                ah[mi][2] = *(const uint32_t*)(p + 16);
                ah[mi][3] = *(const uint32_t*)(p + 8 * HS + 16);
                al[mi][0] = *(const uint32_t*)(q);
                al[mi][1] = *(const uint32_t*)(q + 8 * HS);
                al[mi][2] = *(const uint32_t*)(q + 16);
                al[mi][3] = *(const uint32_t*)(q + 8 * HS + 16);
            }
            #pragma unroll
            for (int ni = 0; ni < 4; ni++) {
                const uint8_t* p = BhiS + (size_t)(wn * 32 + ni * 8 + g) * HS + ko;
                const uint8_t* q = BloS + (size_t)(wn * 32 + ni * 8 + g) * HS + ko;
                uint32_t bh[2] = { *(const uint32_t*)(p), *(const uint32_t*)(p + 16) };
                uint32_t bl[2] = { *(const uint32_t*)(q), *(const uint32_t*)(q + 16) };
                #pragma unroll
                for (int mi = 0; mi < 2; mi++) {
                    MMA_BF16(acc[mi][ni], ah[mi], bh);
                    MMA_BF16(acc[mi][ni], ah[mi], bl);
                    MMA_BF16(acc[mi][ni], al[mi], bh);
                }
            }
        }
        __syncthreads();
    }

    if (kSplit == 1) {
        #pragma unroll
        for (int mi = 0; mi < 2; mi++) {
            int r = wm * 32 + mi * 16 + g;
            #pragma unroll
            for (int ni = 0; ni < 4; ni++) {
                int c = n0 + wn * 32 + ni * 8 + 2 * tg;
                float b0 = bias ? bias[c] : 0.f, b1 = bias ? bias[c+1] : 0.f;
                C[(size_t)r * ldc + c]           = acc[mi][ni][0] + b0;
                C[(size_t)r * ldc + c + 1]       = acc[mi][ni][1] + b1;
                C[(size_t)(r + 8) * ldc + c]     = acc[mi][ni][2] + b0;
                C[(size_t)(r + 8) * ldc + c + 1] = acc[mi][ni][3] + b1;
            }
        }
    } else {
        float* Pz = P + (size_t)by * 64 * N;
        #pragma unroll
        for (int mi = 0; mi < 2; mi++) {
            int r = wm * 32 + mi * 16 + g;
            #pragma unroll
            for (int ni = 0; ni < 4; ni++) {
                int c = n0 + wn * 32 + ni * 8 + 2 * tg;
                Pz[(size_t)r * N + c]           = acc[mi][ni][0];
                Pz[(size_t)r * N + c + 1]       = acc[mi][ni][1];
                Pz[(size_t)(r + 8) * N + c]     = acc[mi][ni][2];
                Pz[(size_t)(r + 8) * N + c + 1] = acc[mi][ni][3];
            }
        }
    }
}

__global__ void __launch_bounds__(256) hmma64_kernel(
    const float* __restrict__ A, int lda, const float* __restrict__ Bm,
    const float* __restrict__ bias, float* __restrict__ C, int ldc,
    float* __restrict__ P, int N, int K, int kSplit)
{
    __shared__ __align__(16) uint8_t smem[384 * HS];
    hmma64_body(A, lda, Bm, bias, C, ldc, P, N, K, kSplit, blockIdx.x, blockIdx.y, smem);
}

// gi (z=0) and gh (z=1) in one launch
__global__ void __launch_bounds__(256) gru_gemms(
    const float* __restrict__ pre_state,
    const float* __restrict__ W_ih, const float* __restrict__ W_hh)
{
    __shared__ __align__(16) uint8_t smem[384 * HS];
    if (blockIdx.z == 0)
        hmma64_body(g_x, XW, W_ih, nullptr, nullptr, 0, g_part, XW, XW, 8,
                    blockIdx.x, blockIdx.y, smem);
    else
        hmma64_body(pre_state, H_, W_hh, nullptr, nullptr, 0, g_part2, XW, H_, 8,
                    blockIdx.x, blockIdx.y, smem);
}

__global__ void splitk_reduce(const float* __restrict__ bias,
                              float* __restrict__ C, int ldc,
                              const float* __restrict__ P, int N, int kSplit)
{
    int idx = blockIdx.x * blockDim.x + threadIdx.x;
    int total = 64 * N;
    if (idx >= total) return;
    int m = idx / N, n = idx - m * N;
    float s = bias ? bias[n] : 0.f;
    for (int z = 0; z < kSplit; z++) s += P[(size_t)z * total + idx];
    C[(size_t)m * ldc + n] = s;
}

// ---- score_c body (validated R7 math) ----
__device__ __forceinline__ void score_c_body(
    const float* __restrict__ enc, const float* __restrict__ W_c,
    const float* __restrict__ b_c, const float* __restrict__ state,
    int sx, int ny, int b, uint8_t* __restrict__ smem)
{
    uint8_t* Ahi = smem;
    uint8_t* Alo = smem + 128 * HS;
    uint8_t* Bhi = smem + 256 * HS;
    uint8_t* Blo = smem + 384 * HS;
    float (*red)[5] = (float(*)[5])(smem + 512 * HS);

    const int tid  = threadIdx.x;
    const int wid  = tid >> 5, lane = tid & 31;
    const int g    = lane >> 2, tg = lane & 3;
    const int wm   = wid >> 2,  wn = wid & 3;
    const int s0   = sx * 128, n0 = ny * 128;

    const int lrow = tid >> 1, lhalf = tid & 1;
    const float* Asrc = enc + ((size_t)(b * S_ + s0 + lrow)) * D2H + lhalf * 16;
    const float* Bsrc = W_c + ((size_t)(n0 + lrow)) * D2H + lhalf * 16;
    uint8_t* AdH = Ahi + lrow * HS + lhalf * 32;
    uint8_t* AdL = Alo + lrow * HS + lhalf * 32;
    uint8_t* BdH = Bhi + lrow * HS + lhalf * 32;
    uint8_t* BdL = Blo + lrow * HS + lhalf * 32;

    float acc[4][4][4];
    #pragma unroll
    for (int mi = 0; mi < 4; mi++)
        #pragma unroll
        for (int ni = 0; ni < 4; ni++)
            #pragma unroll
            for (int q = 0; q < 4; q++) acc[mi][ni][q] = 0.f;

    for (int kc = 0; kc < 32; kc++) {
        #pragma unroll
        for (int i = 0; i < 4; i++) {
            uint2 hi, lo;
            split4(*(const float4*)(Asrc + kc * 32 + i * 4), hi, lo);
            *(uint2*)(AdH + i * 8) = hi;
            *(uint2*)(AdL + i * 8) = lo;
            split4(*(const float4*)(Bsrc + kc * 32 + i * 4), hi, lo);
            *(uint2*)(BdH + i * 8) = hi;
            *(uint2*)(BdL + i * 8) = lo;
        }
        __syncthreads();
        #pragma unroll
        for (int ks = 0; ks < 2; ks++) {
            const int ko = ks * 32 + tg * 4;
            uint32_t ah[4][4], al[4][4];
            #pragma unroll
            for (int mi = 0; mi < 4; mi++) {
                const uint8_t* p = Ahi + (size_t)(wm * 64 + mi * 16 + g) * HS + ko;
                const uint8_t* q = Alo + (size_t)(wm * 64 + mi * 16 + g) * HS + ko;
                ah[mi][0] = *(const uint32_t*)(p);
                ah[mi][1] = *(const uint32_t*)(p + 8 * HS);
                ah[mi][2] = *(const uint32_t*)(p + 16);
                ah[mi][3] = *(const uint32_t*)(p + 8 * HS + 16);
                al[mi][0] = *(const uint32_t*)(q);
                al[mi][1] = *(const uint32_t*)(q + 8 * HS);
                al[mi][2] = *(const uint32_t*)(q + 16);
                al[mi][3] = *(const uint32_t*)(q + 8 * HS + 16);
            }
            #pragma unroll
            for (int ni = 0; ni < 4; ni++) {
                const uint8_t* p = Bhi + (size_t)(wn * 32 + ni * 8 + g) * HS + ko;
                const uint8_t* q = Blo + (size_t)(wn * 32 + ni * 8 + g) * HS + ko;
                uint32_t bh[2] = { *(const uint32_t*)(p), *(const uint32_t*)(p + 16) };
                uint32_t bl[2] = { *(const uint32_t*)(q), *(const uint32_t*)(q + 16) };
                #pragma unroll
                for (int mi = 0; mi < 4; mi++) {
                    MMA_BF16(acc[mi][ni], ah[mi], bh);
                    MMA_BF16(acc[mi][ni], ah[mi], bl);
                    MMA_BF16(acc[mi][ni], al[mi], bh);
                }
            }
        }
        __syncthreads();
    }

    float pr[4][2];
    #pragma unroll
    for (int mi = 0; mi < 4; mi++) { pr[mi][0] = 0.f; pr[mi][1] = 0.f; }
    #pragma unroll
    for (int ni = 0; ni < 4; ni++) {
        int c0 = n0 + wn * 32 + ni * 8 + 2 * tg;
        float bc0 = b_c[c0], bc1 = b_c[c0 + 1];
        float st0 = state[(size_t)b * H_ + c0], st1 = state[(size_t)b * H_ + c0 + 1];
        #pragma unroll
        for (int mi = 0; mi < 4; mi++) {
            pr[mi][0] += tanhf(acc[mi][ni][0] + bc0) * st0 + tanhf(acc[mi][ni][1] + bc1) * st1;
            pr[mi][1] += tanhf(acc[mi][ni][2] + bc0) * st0 + tanhf(acc[mi][ni][3] + bc1) * st1;
        }
    }
    #pragma unroll
    for (int mi = 0; mi < 4; mi++) {
        #pragma unroll
        for (int h = 0; h < 2; h++) {
            float v = pr[mi][h];
            v += __shfl_xor_sync(0xffffffffu, v, 1);
            v += __shfl_xor_sync(0xffffffffu, v, 2);
            if (tg == 0) red[wm * 64 + mi * 16 + h * 8 + g][wn] = v;
        }
    }
    __syncthreads();
    if (tid < 128) {
        float s = red[tid][0] + red[tid][1] + red[tid][2] + red[tid][3];
        g_scpart[(size_t)ny * (B_ * S_) + b * S_ + s0 + tid] = s;
    }
}

// ---- merged scores: score_g (blocks 0..249) + score_c (blocks 250..761) -----
#define SG_BLOCKS (V_ / 128)
__global__ void __launch_bounds__(256) scores_kernel(
    const float* __restrict__ W_o, const float* __restrict__ b_o,
    const float* __restrict__ enc, const float* __restrict__ W_c,
    const float* __restrict__ b_c)
{
    __shared__ __align__(16) uint8_t smem[512 * HS + 128 * 5 * 4];
    if (blockIdx.x < SG_BLOCKS) {
        hmma64_body(g_state, H_, W_o, b_o, g_logits, ML_, nullptr,
                    V_, H_, 1, blockIdx.x, 0, smem);
    } else {
        int idx = blockIdx.x - SG_BLOCKS;          // 0..511
        score_c_body(enc, W_c, b_c, g_state, idx & 1, (idx >> 1) & 3, idx >> 3, smem);
    }
}

// ---- fused attention: strength reduce + embed + scores + softmax + ctx/select
__global__ void __launch_bounds__(1024) attn_fused(
    const float* __restrict__ enc, const int* __restrict__ seq,
    const int* __restrict__ input_idx, const float* __restrict__ ppc,
    const float* __restrict__ table, const float* __restrict__ b_aw)
{
    __shared__ float sm[D2H];
    __shared__ float w[S_], sw[S_];
    __shared__ float red[S_];
    const int b = blockIdx.x, t = threadIdx.x;

    if (t < E_) {
        int idx = input_idx[b];
        if (idx >= V_) idx = 2;
        g_x1[b * X1W + D2H + t] = table[(size_t)idx * E_ + t];
    }
    {
        float s = b_aw[t];
        #pragma unroll
        for (int z = 0; z < 8; z++) s += g_part[(size_t)z * 64 * D2H + b * D2H + t];
        sm[t] = s;
    }
    if (t < S_) {
        int idxb = input_idx[b];
        sw[t] = (seq[b * S_ + t] == idxb) ? ppc[b * S_ + t] : 0.f;
    }
    __syncthreads();

    const int warp = t >> 5, lane = t & 31;
    #pragma unroll
    for (int r = 0; r < 8; r++) {
        int s = warp * 8 + r;
        const float4* row = (const float4*)(enc + ((size_t)b * S_ + s) * D2H);
        float sum = 0.f;
        #pragma unroll
        for (int qi = 0; qi < 8; qi++) {
            int q = lane + qi * 32;
            float4 v = row[q];
            sum += v.x*sm[q*4] + v.y*sm[q*4+1] + v.z*sm[q*4+2] + v.w*sm[q*4+3];
        }
        #pragma unroll
        for (int o = 16; o; o >>= 1) sum += __shfl_down_sync(0xffffffffu, sum, o);
        if (lane == 0) w[s] = sum;
    }
    __syncthreads();

    if (t < S_) red[t] = w[t];
    __syncthreads();
    for (int o = 128; o; o >>= 1) { if (t < o) red[t] = fmaxf(red[t], red[t+o]); __syncthreads(); }
    float mx = red[0];
    __syncthreads();
    if (t < S_) { w[t] = expf(w[t] - mx); red[t] = w[t]; }
    __syncthreads();
    for (int o = 128; o; o >>= 1) { if (t < o) red[t] += red[t+o]; __syncthreads(); }
    float inv = 1.f / red[0];
    __syncthreads();
    if (t < S_) w[t] *= inv;
    __syncthreads();

    const float* e = enc + (size_t)b * S_ * D2H + t;
    float ctx = 0.f, sel = 0.f;
    #pragma unroll 4
    for (int s = 0; s < S_; s++) {
        float v = e[(size_t)s * D2H];
        ctx = fmaf(w[s], v, ctx);
        sel = fmaf(sw[s], v, sel);
    }
    g_x1[b * X1W + t]     = ctx;
    g_x [b * XW + H_ + t] = sel;
}

// ---- fused GRU: gi/gh splitK reduce + gates ----
__global__ void __launch_bounds__(512) gru_fused(
    const float* __restrict__ pre_state,
    const float* __restrict__ b_ih, const float* __restrict__ b_hh,
    float* __restrict__ out_state)
{
    const int b = blockIdx.x, h = threadIdx.x;
    float ir = b_ih[h], iz = b_ih[H_ + h], in_ = b_ih[2*H_ + h];
    float hr = b_hh[h], hz = b_hh[H_ + h], hn  = b_hh[2*H_ + h];
    #pragma unroll
    for (int z = 0; z < 8; z++) {
        size_t base = (size_t)z * 64 * XW + (size_t)b * XW;
        ir  += g_part [base + h];
        iz  += g_part [base + H_ + h];
        in_ += g_part [base + 2*H_ + h];
        hr  += g_part2[base + h];
        hz  += g_part2[base + H_ + h];
        hn  += g_part2[base + 2*H_ + h];
    }
    float r = 1.f / (1.f + expf(-(ir + hr)));
    float z = 1.f / (1.f + expf(-(iz + hz)));
    float n = tanhf(in_ + r * hn);
    float ps = pre_state[b * H_ + h];
    float st = (1.f - z) * n + z * ps;
    g_state[b * H_ + h] = st;
    out_state[b * H_ + h] = st;
}

// ---- fused: scred + big softmax + prob_g write + prob_c scatter ----
__global__ void __launch_bounds__(1024) softmax_probc(
    const int* __restrict__ seq, float* __restrict__ out)
{
    const int b = blockIdx.x, t = threadIdx.x;
    float* row = g_logits + (size_t)b * ML_;
    float* orow = out + (size_t)b * ML_;
    __shared__ float sred[32];
    __shared__ float pc[S_];
    __shared__ int   sq[S_];

    if (t < S_) {
        int idx = b * S_ + t;
        row[V_ + t] = g_scpart[idx] + g_scpart[B_*S_ + idx]
                    + g_scpart[2*B_*S_ + idx] + g_scpart[3*B_*S_ + idx];
        sq[t] = seq[b * S_ + t];
    }
    __syncthreads();

    float m = -1e30f;
    for (int i = t; i < ML_; i += 1024) m = fmaxf(m, row[i]);
    #pragma unroll
    for (int o = 16; o; o >>= 1) m = fmaxf(m, __shfl_xor_sync(0xffffffffu, m, o));
    if ((t & 31) == 0) sred[t >> 5] = m;
    __syncthreads();
    if (t < 32) {
        float x = sred[t];
        #pragma unroll
        for (int o = 16; o; o >>= 1) x = fmaxf(x, __shfl_xor_sync(0xffffffffu, x, o));
        sred[t] = x;
    }
    __syncthreads();
    m = sred[0];
    __syncthreads();
    float sum = 0.f;
    for (int i = t; i < ML_; i += 1024) {
        float e = expf(row[i] - m);
        row[i] = e;
        sum += e;
    }
    #pragma unroll
    for (int o = 16; o; o >>= 1) sum += __shfl_xor_sync(0xffffffffu, sum, o);
    if ((t & 31) == 0) sred[t >> 5] = sum;
    __syncthreads();
    if (t < 32) {
        float x = sred[t];
        #pragma unroll
        for (int o = 16; o; o >>= 1) x += __shfl_xor_sync(0xffffffffu, x, o);
        sred[t] = x;
    }
    __syncthreads();
    float inv = 1.f / sred[0];
    for (int i = t; i < ML_; i += 1024) {
        float v = row[i] * inv;
        if (i < V_) orow[i] = v;
        else { orow[i] = 0.f; pc[i - V_] = v; }
    }
    __syncthreads();

    if (t < S_) {
        int tok = sq[t];
        float s = 0.f;
        bool first = true;
        for (int i = 0; i < S_; i++) {
            bool mq = (sq[i] == tok);
            if (mq) s += pc[i];
            if (mq && i < t) first = false;
        }
        out[(size_t)B_ * ML_ + (size_t)B_ * H_ + b * S_ + t] = s;
        if (first) orow[tok] += s;
    }
}

// ---- launch ----
extern "C" void kernel_launch(void* const* d_in, const int* in_sizes, int n_in,
                              void* d_out, int out_size)
{
    const int*   input_idx = (const int*)  d_in[0];
    const float* enc       = (const float*)d_in[1];
    const int*   seq       = (const int*)  d_in[2];
    const float* pre_state = (const float*)d_in[3];
    const float* ppc       = (const float*)d_in[4];
    const float* table     = (const float*)d_in[5];
    const float* W_aw = (const float*)d_in[6];  const float* b_aw = (const float*)d_in[7];
    const float* W_ac = (const float*)d_in[8];  const float* b_ac = (const float*)d_in[9];
    const float* W_ih = (const float*)d_in[10]; const float* b_ih = (const float*)d_in[11];
    const float* W_hh = (const float*)d_in[12]; const float* b_hh = (const float*)d_in[13];
    const float* W_o  = (const float*)d_in[14]; const float* b_o  = (const float*)d_in[15];
    const float* W_c  = (const float*)d_in[16]; const float* b_c  = (const float*)d_in[17];
    float* out = (float*)d_out;

    // resolve ALL host-passed device-global pointers via cudaGetSymbolAddress
    float *x1, *x, *part;
    cudaGetSymbolAddress((void**)&x1,   g_x1);
    cudaGetSymbolAddress((void**)&x,    g_x);
    cudaGetSymbolAddress((void**)&part, g_part);

    // 1) attn_strength partials: pre_state @ W_aw^T (N=1024, K=512, splitK=8)
    hmma64_kernel<<<dim3(D2H/128, 8), 256>>>(pre_state, H_, W_aw, nullptr, nullptr, 0,
                                             part, D2H, H_, 8);

    // 2) fused: strength reduce + embed + attn scores + softmax + ctx/select
    attn_fused<<<B_, 1024>>>(enc, seq, input_idx, ppc, table, b_aw);

    // 3) attn_reading: x1 @ W_ac^T (N=512, K=1280, splitK=8) -> g_x[:,0:512]
    hmma64_kernel<<<dim3(H_/128, 8), 256>>>(x1, X1W, W_ac, nullptr, nullptr, 0,
                                            part, H_, X1W, 8);
    splitk_reduce<<<(B_*H_ + 255)/256, 256>>>(b_ac, x, XW, part, H_, 8);

    // 4) gi + gh in one launch (splitK=8 each)
    gru_gemms<<<dim3(XW/128, 8, 2), 256>>>(pre_state, W_ih, W_hh);

    // 5) fused GRU (reduces + gates) -> g_state + state output
    gru_fused<<<B_, H_>>>(pre_state, b_ih, b_hh, out + (size_t)B_ * ML_);

    // 6) merged score_g + score_c
    scores_kernel<<<SG_BLOCKS + 512, 256>>>(W_o, b_o, enc, W_c, b_c);

    // 7) fused scred + softmax + prob_g + prob_c
    softmax_probc<<<B_, 1024>>>(seq, out);
}